// round 6
// baseline (speedup 1.0000x reference)
#include <cuda_runtime.h>
#include <math.h>

#define T_STEPS 128
#define BATCH   256
#define OBSD    512
#define ENCD    256
#define HID     512
#define NACT    18
#define NTOT    (T_STEPS * BATCH)   // 32768

#define N_GROUPS 8
#define BLKS_PER_GROUP 16
// scan smem: B frag [12][64][32][2] + A frag double buffer [2][8][2][32][4]
#define BFRAG_FLOATS (12 * 64 * 32 * 2)
#define AFRAG_FLOATS (8 * 2 * 32 * 4)
#define SCAN_SMEM_FLOATS (BFRAG_FLOATS + 2 * AFRAG_FLOATS)
#define SCAN_SMEM_BYTES  (SCAN_SMEM_FLOATS * 4)

// ---------------- scratch (static device globals; no runtime allocation) ----
__device__ float g_h1[(size_t)NTOT * ENCD];
__device__ float g_h2[(size_t)NTOT * ENCD];
__device__ float g_gx[(size_t)NTOT * 3 * HID];
__device__ float g_hidden[(size_t)NTOT * HID];
__device__ float g_state[2][BATCH * HID];
__device__ float g_bcomb[3 * HID];

// ---------------------------------------------------------------------------
__device__ __forceinline__ unsigned f2tf32(float f) {
    unsigned u;
    asm("cvt.rna.tf32.f32 %0, %1;" : "=r"(u) : "f"(f));
    return u;
}

__device__ __forceinline__ void mma_tf32(float d[4], const unsigned a[4], const unsigned b[2]) {
    asm volatile(
        "mma.sync.aligned.m16n8k8.row.col.f32.tf32.tf32.f32 "
        "{%0,%1,%2,%3}, {%4,%5,%6,%7}, {%8,%9}, {%0,%1,%2,%3};"
        : "+f"(d[0]), "+f"(d[1]), "+f"(d[2]), "+f"(d[3])
        : "r"(a[0]), "r"(a[1]), "r"(a[2]), "r"(a[3]), "r"(b[0]), "r"(b[1]));
}

__device__ __forceinline__ float sigmoidf_(float x) {
    return 1.f / (1.f + expf(-x));
}

__global__ void init_bias_kernel(const float* __restrict__ b_ih,
                                 const float* __restrict__ b_hh)
{
    int i = blockIdx.x * 256 + threadIdx.x;
    if (i < 3 * HID)
        g_bcomb[i] = b_ih[i] + ((i < 2 * HID) ? b_hh[i] : 0.f);
}

// ---------------------------------------------------------------------------
// Generic C[M,Nc] = act(A[M,K] @ W[Nc,K]^T + bias) using tf32 mma.
// BM=128, BN=64, BK=16, 256 threads (8 warps, 4m x 2n), warptile 32x32.
// Fragment-layout smem: consumer does LDS.128 (A) / LDS.64 (W) per fragment.
// ---------------------------------------------------------------------------
template <bool RELU>
__global__ __launch_bounds__(256)
void gemm_tf32_kernel(const float* __restrict__ A,
                      const float* __restrict__ W,
                      const float* __restrict__ bias,
                      float* __restrict__ C,
                      int M, int Nc, int K)
{
    // Afrag: [buf2][k8(2)][mt(8)][lane(32)][4]  = 2*2048 floats
    // Wfrag: [buf2][k8(2)][nt(8)][lane(32)][2]  = 2*1024 floats
    __shared__ float Af[2][2 * 8 * 32 * 4];
    __shared__ float Wf[2][2 * 8 * 32 * 2];

    const int tid  = threadIdx.x;
    const int warp = tid >> 5;
    const int lane = tid & 31;
    const int g    = lane >> 2;
    const int tg   = lane & 3;
    const int mwarp = warp & 3;       // 4 m-warps
    const int nwarp = warp >> 2;      // 2 n-warps
    const int row0 = blockIdx.y * 128;
    const int col0 = blockIdx.x * 64;

    float acc[2][4][4];
#pragma unroll
    for (int i = 0; i < 2; i++)
#pragma unroll
        for (int j = 0; j < 4; j++)
#pragma unroll
            for (int q = 0; q < 4; q++) acc[i][j][q] = 0.f;

    // writer decode (per thread, constant over tiles)
    // A: i = tid + l*256 -> r = i>>2, k8=(i&3)>>1, khi=(i&3)&1
    // W: r = tid>>2, k8=(tid&3)>>1, khi=(tid&3)&1
    float4 ra[2], rw;
#pragma unroll
    for (int l = 0; l < 2; l++) {
        int i = tid + l * 256;
        ra[l] = *(const float4*)(A + (size_t)(row0 + (i >> 2)) * K + (i & 3) * 4);
    }
    rw = *(const float4*)(W + (size_t)(col0 + (tid >> 2)) * K + (tid & 3) * 4);

    const int nk0 = K / 16;
    for (int kt = 0; kt < nk0; kt++) {
        const int buf = kt & 1;
        // ---- store fragments ----
#pragma unroll
        for (int l = 0; l < 2; l++) {
            int i = tid + l * 256;
            int r = i >> 2;
            int k8 = (i & 3) >> 1, khi = i & 1;
            int mt = r >> 4, gw = r & 7, half = (r >> 3) & 1;
            float* d = Af[buf] + (size_t)((k8 * 8 + mt) * 32 + gw * 4) * 4 + (half + 2 * khi);
            d[0]  = __uint_as_float(f2tf32(ra[l].x));
            d[4]  = __uint_as_float(f2tf32(ra[l].y));
            d[8]  = __uint_as_float(f2tf32(ra[l].z));
            d[12] = __uint_as_float(f2tf32(ra[l].w));
        }
        {
            int r = tid >> 2;
            int k8 = (tid & 3) >> 1, khi = tid & 1;
            int nt = r >> 3, gw = r & 7;
            float* d = Wf[buf] + (size_t)((k8 * 8 + nt) * 32 + gw * 4) * 2 + khi;
            d[0] = __uint_as_float(f2tf32(rw.x));
            d[2] = __uint_as_float(f2tf32(rw.y));
            d[4] = __uint_as_float(f2tf32(rw.z));
            d[6] = __uint_as_float(f2tf32(rw.w));
        }
        __syncthreads();

        if (kt + 1 < nk0) {
            int k0n = (kt + 1) * 16;
#pragma unroll
            for (int l = 0; l < 2; l++) {
                int i = tid + l * 256;
                ra[l] = *(const float4*)(A + (size_t)(row0 + (i >> 2)) * K + k0n + (i & 3) * 4);
            }
            rw = *(const float4*)(W + (size_t)(col0 + (tid >> 2)) * K + k0n + (tid & 3) * 4);
        }

#pragma unroll
        for (int k8 = 0; k8 < 2; k8++) {
            unsigned af[2][4], bf[4][2];
#pragma unroll
            for (int mf = 0; mf < 2; mf++) {
                int mt = mwarp * 2 + mf;
                float4 v = *(const float4*)(Af[buf] + (size_t)((k8 * 8 + mt) * 32 + lane) * 4);
                af[mf][0] = __float_as_uint(v.x);
                af[mf][1] = __float_as_uint(v.y);
                af[mf][2] = __float_as_uint(v.z);
                af[mf][3] = __float_as_uint(v.w);
            }
#pragma unroll
            for (int nf = 0; nf < 4; nf++) {
                int nt = nwarp * 4 + nf;
                float2 w2 = *(const float2*)(Wf[buf] + (size_t)((k8 * 8 + nt) * 32 + lane) * 2);
                bf[nf][0] = __float_as_uint(w2.x);
                bf[nf][1] = __float_as_uint(w2.y);
            }
#pragma unroll
            for (int mf = 0; mf < 2; mf++)
#pragma unroll
                for (int nf = 0; nf < 4; nf++) mma_tf32(acc[mf][nf], af[mf], bf[nf]);
        }
    }

#pragma unroll
    for (int mf = 0; mf < 2; mf++) {
#pragma unroll
        for (int nf = 0; nf < 4; nf++) {
            int r = row0 + mwarp * 32 + mf * 16 + g;
            int c = col0 + nwarp * 32 + nf * 8 + tg * 2;
            float b0v = bias[c], b1v = bias[c + 1];
            float v0 = acc[mf][nf][0] + b0v;
            float v1 = acc[mf][nf][1] + b1v;
            float v2 = acc[mf][nf][2] + b0v;
            float v3 = acc[mf][nf][3] + b1v;
            if (RELU) {
                v0 = fmaxf(v0, 0.f); v1 = fmaxf(v1, 0.f);
                v2 = fmaxf(v2, 0.f); v3 = fmaxf(v3, 0.f);
            }
            *(float2*)&C[(size_t)r * Nc + c]       = make_float2(v0, v1);
            *(float2*)&C[(size_t)(r + 8) * Nc + c] = make_float2(v2, v3);
        }
    }
}

// ---------------------------------------------------------------------------
// Persistent GRU scan. 8 clusters (batch groups) x 16 CTAs (h-col tiles).
// Hardware cluster barrier between steps. w_hh slice resident in smem in
// mma-fragment layout; A staged in fragment layout too. Final step writes
// directly to the output buffer.
// ---------------------------------------------------------------------------
__global__ __launch_bounds__(256)
void gru_scan_kernel(const float* __restrict__ gru_st,
                     const float* __restrict__ w_hh,
                     const float* __restrict__ b_hh,
                     const float* __restrict__ done,
                     float* __restrict__ out_state)
{
    extern __shared__ float sm[];
    float* Bf  = sm;                    // [nt(12)][k8(64)][lane(32)][2]
    float* Afr = sm + BFRAG_FLOATS;     // [buf2][k8(8)][mt(2)][lane(32)][4]

    const int tid  = threadIdx.x;
    const int warp = tid >> 5;
    const int lane = tid & 31;
    const int g    = lane >> 2;
    const int tg   = lane & 3;
    const int bid  = blockIdx.x;
    const int col0 = (bid & 15) * 32;     // h-col block
    const int gid  = bid >> 4;            // batch group == cluster
    const int row0 = gid * 32;
    const int mt_c   = warp & 1;          // consumer m16 tile
    const int warp_m = mt_c * 16;
    const int ntb    = warp >> 1;         // 0..3: 8-col slot within gate
    const int warp_hn = ntb * 8;

    // ---- preload w_hh slice (96 combined rows x 512 K) into fragment layout
    for (int i = tid; i < 96 * 64; i += 256) {
        int cr = i >> 6;                 // combined row 0..95
        int k8 = i & 63;                 // k-octet 0..63
        int gate = cr >> 5, lc = cr & 31;
        const float* wrow = w_hh + (size_t)(gate * HID + col0 + lc) * HID + k8 * 8;
        float4 w0 = *(const float4*)(wrow);
        float4 w1 = *(const float4*)(wrow + 4);
        int nt = cr >> 3, gg = cr & 7;
        float* dst = Bf + (size_t)((nt * 64 + k8) * 32 + gg * 4) * 2;
        float4 o0 = make_float4(__uint_as_float(f2tf32(w0.x)), __uint_as_float(f2tf32(w1.x)),
                                __uint_as_float(f2tf32(w0.y)), __uint_as_float(f2tf32(w1.y)));
        float4 o1 = make_float4(__uint_as_float(f2tf32(w0.z)), __uint_as_float(f2tf32(w1.z)),
                                __uint_as_float(f2tf32(w0.w)), __uint_as_float(f2tf32(w1.w)));
        *(float4*)(dst)     = o0;
        *(float4*)(dst + 4) = o1;
    }

    // n-gate hidden bias for this thread's 2 cols
    const int ccol = col0 + warp_hn + tg * 2;
    const float2 bn2 = *(const float2*)(b_hh + 2 * HID + ccol);

    // A staging decode (constant over steps)
    const int r_a  = tid >> 3;           // batch row 0..31
    const int c4a  = (tid & 7) * 4;      // k offset within 32
    const int k8f  = c4a >> 3;           // 0..3
    const int khif = (c4a >> 2) & 1;
    const int mt_w = r_a >> 4, g_w = r_a & 7, half_w = (r_a >> 3) & 1;
    const int j_w  = half_w + 2 * khif;
    const int rr0  = warp_m + g;         // gate-math rows
    const int rr1  = rr0 + 8;

    __syncthreads();

    float* sb0 = g_state[0];
    float* sb1 = g_state[1];

    for (int t = 0; t < T_STEPS; t++) {
        const float* sin = (t == 0) ? gru_st : ((t & 1) ? sb1 : sb0);
        float*       sout = (t == T_STEPS - 1) ? out_state : ((t & 1) ? sb0 : sb1);

        const float m_a = 1.0f - __ldg(done + t * BATCH + row0 + r_a);
        const float* arow = sin + (size_t)(row0 + r_a) * HID;
        float4 ra0 = __ldcg((const float4*)(arow + c4a));
        float4 ra1 = __ldcg((const float4*)(arow + 32 + c4a));

        // prefetch gx / h_prev for gate math (hidden under mma loop)
        const float* gx0 = g_gx + ((size_t)(t * BATCH + row0 + rr0)) * (3 * HID);
        const float* gx1 = g_gx + ((size_t)(t * BATCH + row0 + rr1)) * (3 * HID);
        float2 xr0 = *(const float2*)(gx0 + ccol);
        float2 xz0 = *(const float2*)(gx0 + HID + ccol);
        float2 xn0 = *(const float2*)(gx0 + 2 * HID + ccol);
        float2 xr1 = *(const float2*)(gx1 + ccol);
        float2 xz1 = *(const float2*)(gx1 + HID + ccol);
        float2 xn1 = *(const float2*)(gx1 + 2 * HID + ccol);
        float2 hp0 = __ldcg((const float2*)(sin + (size_t)(row0 + rr0) * HID + ccol));
        float2 hp1 = __ldcg((const float2*)(sin + (size_t)(row0 + rr1) * HID + ccol));
        const float m0 = 1.0f - __ldg(done + t * BATCH + row0 + rr0);
        const float m1 = 1.0f - __ldg(done + t * BATCH + row0 + rr1);

        float acc[3][4];
#pragma unroll
        for (int gt = 0; gt < 3; gt++)
#pragma unroll
            for (int q = 0; q < 4; q++) acc[gt][q] = 0.f;

        // ---- K loop: 8 phases of 64 ----
#pragma unroll 2
        for (int p = 0; p < 8; p++) {
            float* Ab = Afr + (p & 1) * AFRAG_FLOATS;
            {
                float* d0 = Ab + (size_t)((k8f * 2 + mt_w) * 32 + g_w * 4) * 4 + j_w;
                d0[0]  = __uint_as_float(f2tf32(ra0.x * m_a));
                d0[4]  = __uint_as_float(f2tf32(ra0.y * m_a));
                d0[8]  = __uint_as_float(f2tf32(ra0.z * m_a));
                d0[12] = __uint_as_float(f2tf32(ra0.w * m_a));
                float* d1 = Ab + (size_t)(((k8f + 4) * 2 + mt_w) * 32 + g_w * 4) * 4 + j_w;
                d1[0]  = __uint_as_float(f2tf32(ra1.x * m_a));
                d1[4]  = __uint_as_float(f2tf32(ra1.y * m_a));
                d1[8]  = __uint_as_float(f2tf32(ra1.z * m_a));
                d1[12] = __uint_as_float(f2tf32(ra1.w * m_a));
            }
            if (p < 7) {
                ra0 = __ldcg((const float4*)(arow + (p + 1) * 64 + c4a));
                ra1 = __ldcg((const float4*)(arow + (p + 1) * 64 + 32 + c4a));
            }
            __syncthreads();

#pragma unroll
            for (int kk = 0; kk < 8; kk++) {
                float4 v = *(const float4*)(Ab + (size_t)((kk * 2 + mt_c) * 32 + lane) * 4);
                unsigned af[4] = { __float_as_uint(v.x), __float_as_uint(v.y),
                                   __float_as_uint(v.z), __float_as_uint(v.w) };
                int k8 = p * 8 + kk;
#pragma unroll
                for (int gt = 0; gt < 3; gt++) {
                    int nt = gt * 4 + ntb;
                    float2 b2 = *(const float2*)(Bf + (size_t)((nt * 64 + k8) * 32 + lane) * 2);
                    unsigned bf[2] = { __float_as_uint(b2.x), __float_as_uint(b2.y) };
                    mma_tf32(acc[gt], af, bf);
                }
            }
        }

        // ---- fused gate math in registers ----
        {
            float r, z, n;
            r = sigmoidf_(xr0.x + acc[0][0]);
            z = sigmoidf_(xz0.x + acc[1][0]);
            n = tanhf(xn0.x + r * (acc[2][0] + bn2.x));
            float hn0x = (1.f - z) * n + z * (hp0.x * m0);
            r = sigmoidf_(xr0.y + acc[0][1]);
            z = sigmoidf_(xz0.y + acc[1][1]);
            n = tanhf(xn0.y + r * (acc[2][1] + bn2.y));
            float hn0y = (1.f - z) * n + z * (hp0.y * m0);
            r = sigmoidf_(xr1.x + acc[0][2]);
            z = sigmoidf_(xz1.x + acc[1][2]);
            n = tanhf(xn1.x + r * (acc[2][2] + bn2.x));
            float hn1x = (1.f - z) * n + z * (hp1.x * m1);
            r = sigmoidf_(xr1.y + acc[0][3]);
            z = sigmoidf_(xz1.y + acc[1][3]);
            n = tanhf(xn1.y + r * (acc[2][3] + bn2.y));
            float hn1y = (1.f - z) * n + z * (hp1.y * m1);

            float2 o0 = make_float2(hn0x, hn0y);
            float2 o1 = make_float2(hn1x, hn1y);
            *(float2*)(sout + (size_t)(row0 + rr0) * HID + ccol) = o0;
            *(float2*)(sout + (size_t)(row0 + rr1) * HID + ccol) = o1;
            *(float2*)(g_hidden + ((size_t)(t * BATCH + row0 + rr0)) * HID + ccol) = o0;
            *(float2*)(g_hidden + ((size_t)(t * BATCH + row0 + rr1)) * HID + ccol) = o1;
        }

        // ---- hardware cluster barrier (skip after last step) ----
        if (t < T_STEPS - 1) {
            asm volatile("barrier.cluster.arrive.aligned;" ::: "memory");
            asm volatile("barrier.cluster.wait.aligned;" ::: "memory");
        }
    }
}

// ---------------------------------------------------------------------------
// Heads: one warp per row n.
// ---------------------------------------------------------------------------
__global__ __launch_bounds__(256)
void heads_kernel(const int* __restrict__ action,
                  const float* __restrict__ w_actor,
                  const float* __restrict__ b_actor,
                  const float* __restrict__ w_critic,
                  const float* __restrict__ b_critic,
                  float* __restrict__ out)
{
    __shared__ float s_wa[NACT * HID];
    __shared__ float s_wc[HID];
    __shared__ float s_ba[NACT];

    const int tid = threadIdx.x;
    for (int i = tid; i < NACT * HID; i += 256) s_wa[i] = w_actor[i];
    for (int i = tid; i < HID; i += 256) s_wc[i] = w_critic[i];
    if (tid < NACT) s_ba[tid] = b_actor[tid];
    __syncthreads();

    const int warp = tid >> 5;
    const int lane = tid & 31;
    const int n = blockIdx.x * 8 + warp;

    const float* hrow = g_hidden + (size_t)n * HID;
    float h[16];
#pragma unroll
    for (int i = 0; i < 16; i++) h[i] = hrow[lane + 32 * i];

    float l[NACT];
#pragma unroll
    for (int a = 0; a < NACT; a++) {
        float p = 0.f;
        const float* wa = s_wa + a * HID;
#pragma unroll
        for (int i = 0; i < 16; i++) p += h[i] * wa[lane + 32 * i];
#pragma unroll
        for (int o = 16; o > 0; o >>= 1) p += __shfl_xor_sync(0xffffffffu, p, o);
        l[a] = p + s_ba[a];
    }

    float v = 0.f;
#pragma unroll
    for (int i = 0; i < 16; i++) v += h[i] * s_wc[lane + 32 * i];
#pragma unroll
    for (int o = 16; o > 0; o >>= 1) v += __shfl_xor_sync(0xffffffffu, v, o);
    v += b_critic[0];

    float mx = l[0];
#pragma unroll
    for (int a = 1; a < NACT; a++) mx = fmaxf(mx, l[a]);
    float s = 0.f;
#pragma unroll
    for (int a = 0; a < NACT; a++) s += expf(l[a] - mx);
    float lse = mx + logf(s);

    float ent = 0.f;
#pragma unroll
    for (int a = 0; a < NACT; a++) ent += expf(l[a] - lse) * (lse - l[a]);

    int act = action[n];
    float lp = 0.f;
#pragma unroll
    for (int a = 0; a < NACT; a++) lp += (a == act) ? (l[a] - lse) : 0.f;

    if (lane == 0) {
        out[n] = lp;
        out[NTOT + n] = ent;
        out[2 * NTOT + n] = v;
    }
}

// ---------------------------------------------------------------------------
extern "C" void kernel_launch(void* const* d_in, const int* in_sizes, int n_in,
                              void* d_out, int out_size)
{
    const float* x        = (const float*)d_in[0];
    const float* gru_st   = (const float*)d_in[1];
    const float* done     = (const float*)d_in[2];
    const int*   action   = (const int*)  d_in[3];
    const float* w1       = (const float*)d_in[4];
    const float* b1       = (const float*)d_in[5];
    const float* w2       = (const float*)d_in[6];
    const float* b2       = (const float*)d_in[7];
    const float* w_ih     = (const float*)d_in[8];
    const float* w_hh     = (const float*)d_in[9];
    const float* b_ih     = (const float*)d_in[10];
    const float* b_hh     = (const float*)d_in[11];
    const float* w_actor  = (const float*)d_in[12];
    const float* b_actor  = (const float*)d_in[13];
    const float* w_critic = (const float*)d_in[14];
    const float* b_critic = (const float*)d_in[15];
    float* out = (float*)d_out;

    float *h1, *h2, *gx, *bc;
    cudaGetSymbolAddress((void**)&h1, g_h1);
    cudaGetSymbolAddress((void**)&h2, g_h2);
    cudaGetSymbolAddress((void**)&gx, g_gx);
    cudaGetSymbolAddress((void**)&bc, g_bcomb);

    static int attrs_set = 0;
    if (!attrs_set) {
        cudaFuncSetAttribute(gru_scan_kernel,
                             cudaFuncAttributeMaxDynamicSharedMemorySize,
                             SCAN_SMEM_BYTES);
        cudaFuncSetAttribute(gru_scan_kernel,
                             cudaFuncAttributeNonPortableClusterSizeAllowed, 1);
        attrs_set = 1;
    }

    // combined bias (b_ih + b_hh for r,z gates)
    init_bias_kernel<<<(3 * HID + 255) / 256, 256>>>(b_ih, b_hh);

    // encoder layer 1: (N,512)@(512,256)^T -> h1
    gemm_tf32_kernel<true><<<dim3(ENCD / 64, NTOT / 128), 256>>>(
        x, w1, b1, h1, NTOT, ENCD, OBSD);
    // encoder layer 2: (N,256)@(256,256)^T -> h2
    gemm_tf32_kernel<true><<<dim3(ENCD / 64, NTOT / 128), 256>>>(
        h1, w2, b2, h2, NTOT, ENCD, ENCD);
    // input-side gates (bias = b_ih + b_hh[r,z]): (N,256)@(256,1536)^T -> gx
    gemm_tf32_kernel<false><<<dim3(3 * HID / 64, NTOT / 128), 256>>>(
        h2, w_ih, bc, gx, NTOT, 3 * HID, ENCD);

    // persistent GRU scan: 8 clusters of 16 CTAs
    {
        cudaLaunchConfig_t cfg = {};
        cfg.gridDim = dim3(N_GROUPS * BLKS_PER_GROUP, 1, 1);
        cfg.blockDim = dim3(256, 1, 1);
        cfg.dynamicSmemBytes = SCAN_SMEM_BYTES;
        cfg.stream = 0;
        cudaLaunchAttribute at[1];
        at[0].id = cudaLaunchAttributeClusterDimension;
        at[0].val.clusterDim.x = BLKS_PER_GROUP;
        at[0].val.clusterDim.y = 1;
        at[0].val.clusterDim.z = 1;
        cfg.attrs = at;
        cfg.numAttrs = 1;
        float* out_state = out + 3 * NTOT;
        cudaLaunchKernelEx(&cfg, gru_scan_kernel, gru_st, w_hh, b_hh, done, out_state);
    }

    heads_kernel<<<NTOT / 8, 256>>>(action, w_actor, b_actor, w_critic, b_critic, out);
}

// round 7
// speedup vs baseline: 1.6483x; 1.6483x over previous
#include <cuda_runtime.h>
#include <math.h>

#define T_STEPS 128
#define BATCH   256
#define OBSD    512
#define ENCD    256
#define HID     512
#define NACT    18
#define NTOT    (T_STEPS * BATCH)   // 32768

#define N_GROUPS 8
#define BLKS_PER_GROUP 16
// scan smem: B frag [12][64][32][2] + A frag double buffer [2][16][2][32][4]
#define BFRAG_FLOATS (12 * 64 * 32 * 2)      // 49152
#define AFRAG_FLOATS (16 * 2 * 32 * 4)       // 4096
#define SCAN_SMEM_FLOATS (BFRAG_FLOATS + 2 * AFRAG_FLOATS)
#define SCAN_SMEM_BYTES  (SCAN_SMEM_FLOATS * 4)   // 229376

// ---------------- scratch (static device globals; no runtime allocation) ----
__device__ float g_h1[(size_t)NTOT * ENCD];
__device__ float g_h2[(size_t)NTOT * ENCD];
__device__ float g_gx[(size_t)NTOT * 3 * HID];
__device__ float g_hidden[(size_t)NTOT * HID];
__device__ float g_bcomb[3 * HID];
__device__ unsigned g_barriers[N_GROUPS][32];   // 128B-padded per-group counters

// ---------------------------------------------------------------------------
__device__ __forceinline__ unsigned f2tf32(float f) {
    unsigned u;
    asm("cvt.rna.tf32.f32 %0, %1;" : "=r"(u) : "f"(f));
    return u;
}

__device__ __forceinline__ void mma_tf32(float d[4], const unsigned a[4], const unsigned b[2]) {
    asm volatile(
        "mma.sync.aligned.m16n8k8.row.col.f32.tf32.tf32.f32 "
        "{%0,%1,%2,%3}, {%4,%5,%6,%7}, {%8,%9}, {%0,%1,%2,%3};"
        : "+f"(d[0]), "+f"(d[1]), "+f"(d[2]), "+f"(d[3])
        : "r"(a[0]), "r"(a[1]), "r"(a[2]), "r"(a[3]), "r"(b[0]), "r"(b[1]));
}

__device__ __forceinline__ float sigmoidf_(float x) {
    return 1.f / (1.f + expf(-x));
}

__global__ void init_kernel(const float* __restrict__ b_ih,
                            const float* __restrict__ b_hh)
{
    int i = blockIdx.x * 256 + threadIdx.x;
    if (i < N_GROUPS) g_barriers[i][0] = 0u;
    if (i < 3 * HID)
        g_bcomb[i] = b_ih[i] + ((i < 2 * HID) ? b_hh[i] : 0.f);
}

// ---------------------------------------------------------------------------
// Generic C[M,Nc] = act(A[M,K] @ W[Nc,K]^T + bias) using tf32 mma.
// BM=128, BN=64, BK=16, 256 threads (8 warps, 4m x 2n), warptile 32x32.
// (R5 row-layout version — measured fastest.)
// ---------------------------------------------------------------------------
template <bool RELU>
__global__ __launch_bounds__(256)
void gemm_tf32_kernel(const float* __restrict__ A,
                      const float* __restrict__ W,
                      const float* __restrict__ bias,
                      float* __restrict__ C,
                      int M, int Nc, int K)
{
    __shared__ float As[128][18];
    __shared__ float Ws[64][18];

    const int tid  = threadIdx.x;
    const int warp = tid >> 5;
    const int lane = tid & 31;
    const int g    = lane >> 2;
    const int tg   = lane & 3;
    const int warp_m = (warp & 3) * 32;
    const int warp_n = (warp >> 2) * 32;
    const int row0 = blockIdx.y * 128;
    const int col0 = blockIdx.x * 64;

    float acc[2][4][4];
#pragma unroll
    for (int i = 0; i < 2; i++)
#pragma unroll
        for (int j = 0; j < 4; j++)
#pragma unroll
            for (int q = 0; q < 4; q++) acc[i][j][q] = 0.f;

    float4 ra[2], rw;
#pragma unroll
    for (int l = 0; l < 2; l++) {
        int i = tid + l * 256;
        ra[l] = *(const float4*)(A + (size_t)(row0 + (i >> 2)) * K + (i & 3) * 4);
    }
    rw = *(const float4*)(W + (size_t)(col0 + (tid >> 2)) * K + (tid & 3) * 4);

    for (int k0 = 0; k0 < K; k0 += 16) {
#pragma unroll
        for (int l = 0; l < 2; l++) {
            int i = tid + l * 256;
            int r = i >> 2, c = (i & 3) * 4;
            As[r][c + 0] = __uint_as_float(f2tf32(ra[l].x));
            As[r][c + 1] = __uint_as_float(f2tf32(ra[l].y));
            As[r][c + 2] = __uint_as_float(f2tf32(ra[l].z));
            As[r][c + 3] = __uint_as_float(f2tf32(ra[l].w));
        }
        {
            int r = tid >> 2, c = (tid & 3) * 4;
            Ws[r][c + 0] = __uint_as_float(f2tf32(rw.x));
            Ws[r][c + 1] = __uint_as_float(f2tf32(rw.y));
            Ws[r][c + 2] = __uint_as_float(f2tf32(rw.z));
            Ws[r][c + 3] = __uint_as_float(f2tf32(rw.w));
        }
        __syncthreads();

        if (k0 + 16 < K) {
#pragma unroll
            for (int l = 0; l < 2; l++) {
                int i = tid + l * 256;
                ra[l] = *(const float4*)(A + (size_t)(row0 + (i >> 2)) * K + k0 + 16 + (i & 3) * 4);
            }
            rw = *(const float4*)(W + (size_t)(col0 + (tid >> 2)) * K + k0 + 16 + (tid & 3) * 4);
        }

#pragma unroll
        for (int ks = 0; ks < 16; ks += 8) {
            unsigned af[2][4], bf[4][2];
#pragma unroll
            for (int mf = 0; mf < 2; mf++) {
                int br = warp_m + mf * 16;
                af[mf][0] = __float_as_uint(As[br + g][ks + tg]);
                af[mf][1] = __float_as_uint(As[br + g + 8][ks + tg]);
                af[mf][2] = __float_as_uint(As[br + g][ks + tg + 4]);
                af[mf][3] = __float_as_uint(As[br + g + 8][ks + tg + 4]);
            }
#pragma unroll
            for (int nf = 0; nf < 4; nf++) {
                int bn = warp_n + nf * 8;
                bf[nf][0] = __float_as_uint(Ws[bn + g][ks + tg]);
                bf[nf][1] = __float_as_uint(Ws[bn + g][ks + tg + 4]);
            }
#pragma unroll
            for (int mf = 0; mf < 2; mf++)
#pragma unroll
                for (int nf = 0; nf < 4; nf++) mma_tf32(acc[mf][nf], af[mf], bf[nf]);
        }
        __syncthreads();
    }

#pragma unroll
    for (int mf = 0; mf < 2; mf++) {
#pragma unroll
        for (int nf = 0; nf < 4; nf++) {
            int r = row0 + warp_m + mf * 16 + g;
            int c = col0 + warp_n + nf * 8 + tg * 2;
            float b0v = bias[c], b1v = bias[c + 1];
            float v0 = acc[mf][nf][0] + b0v;
            float v1 = acc[mf][nf][1] + b1v;
            float v2 = acc[mf][nf][2] + b0v;
            float v3 = acc[mf][nf][3] + b1v;
            if (RELU) {
                v0 = fmaxf(v0, 0.f); v1 = fmaxf(v1, 0.f);
                v2 = fmaxf(v2, 0.f); v3 = fmaxf(v3, 0.f);
            }
            *(float2*)&C[(size_t)r * Nc + c]       = make_float2(v0, v1);
            *(float2*)&C[(size_t)(r + 8) * Nc + c] = make_float2(v2, v3);
        }
    }
}

// ---------------------------------------------------------------------------
// Persistent GRU scan. 128 blocks = 8 batch groups x 16 h-col tiles.
// Padded per-group atomic barriers. w_hh slice resident in smem (frag layout).
// 4 K-phases of 128 per step (4 syncthreads). State lives in g_hidden rows.
// gx[t+1] prefetched before the barrier spin.
// ---------------------------------------------------------------------------
__global__ __launch_bounds__(256)
void gru_scan_kernel(const float* __restrict__ gru_st,
                     const float* __restrict__ w_hh,
                     const float* __restrict__ b_hh,
                     const float* __restrict__ done,
                     float* __restrict__ out_state)
{
    extern __shared__ float sm[];
    float* Bf  = sm;                    // [nt(12)][k8(64)][lane(32)][2]
    float* Afr = sm + BFRAG_FLOATS;     // [buf2][k8(16)][mt(2)][lane(32)][4]

    const int tid  = threadIdx.x;
    const int warp = tid >> 5;
    const int lane = tid & 31;
    const int g    = lane >> 2;
    const int tg   = lane & 3;
    const int bid  = blockIdx.x;
    const int col0 = (bid & 15) * 32;     // h-col block
    const int gid  = bid >> 4;            // batch group
    const int row0 = gid * 32;
    const int mt_c   = warp & 1;          // consumer m16 tile
    const int ntb    = warp >> 1;         // 0..3: 8-col slot within gate
    const int warp_hn = ntb * 8;

    // ---- preload w_hh slice into fragment layout ----
    for (int i = tid; i < 96 * 64; i += 256) {
        int cr = i >> 6;
        int k8 = i & 63;
        int gate = cr >> 5, lc = cr & 31;
        const float* wrow = w_hh + (size_t)(gate * HID + col0 + lc) * HID + k8 * 8;
        float4 w0 = *(const float4*)(wrow);
        float4 w1 = *(const float4*)(wrow + 4);
        int nt = cr >> 3, gg = cr & 7;
        float* dst = Bf + (size_t)((nt * 64 + k8) * 32 + gg * 4) * 2;
        float4 o0 = make_float4(__uint_as_float(f2tf32(w0.x)), __uint_as_float(f2tf32(w1.x)),
                                __uint_as_float(f2tf32(w0.y)), __uint_as_float(f2tf32(w1.y)));
        float4 o1 = make_float4(__uint_as_float(f2tf32(w0.z)), __uint_as_float(f2tf32(w1.z)),
                                __uint_as_float(f2tf32(w0.w)), __uint_as_float(f2tf32(w1.w)));
        *(float4*)(dst)     = o0;
        *(float4*)(dst + 4) = o1;
    }

    const int ccol = col0 + warp_hn + tg * 2;
    const float2 bn2 = *(const float2*)(b_hh + 2 * HID + ccol);

    // A staging decode (constant over steps)
    const int r_a  = tid >> 3;             // batch row 0..31
    const int c4a  = (tid & 7) * 4;        // k offset within 32
    const int k8f  = c4a >> 3;             // 0..3
    const int khif = (c4a >> 2) & 1;
    const int mt_w = r_a >> 4, g_w = r_a & 7, half_w = (r_a >> 3) & 1;
    const int j_w  = half_w + 2 * khif;
    const int rr0  = (warp & 1) * 16 + g;  // gate-math rows
    const int rr1  = rr0 + 8;

    __syncthreads();

    // ---- prefetch step-0 inputs ----
    float m_a = 1.0f - __ldg(done + row0 + r_a);
    float m0  = 1.0f - __ldg(done + row0 + rr0);
    float m1  = 1.0f - __ldg(done + row0 + rr1);
    const float* gx0p = g_gx + ((size_t)(row0 + rr0)) * (3 * HID);
    const float* gx1p = g_gx + ((size_t)(row0 + rr1)) * (3 * HID);
    float2 xr0 = *(const float2*)(gx0p + ccol);
    float2 xz0 = *(const float2*)(gx0p + HID + ccol);
    float2 xn0 = *(const float2*)(gx0p + 2 * HID + ccol);
    float2 xr1 = *(const float2*)(gx1p + ccol);
    float2 xz1 = *(const float2*)(gx1p + HID + ccol);
    float2 xn1 = *(const float2*)(gx1p + 2 * HID + ccol);

    for (int t = 0; t < T_STEPS; t++) {
        const float* sin = (t == 0) ? gru_st
                                    : (g_hidden + (size_t)(t - 1) * BATCH * HID);
        float* sout = g_hidden + (size_t)t * BATCH * HID;

        const float* arow = sin + (size_t)(row0 + r_a) * HID;
        float4 ra[4];
#pragma unroll
        for (int kc = 0; kc < 4; kc++)
            ra[kc] = __ldcg((const float4*)(arow + kc * 32 + c4a));
        float2 hp0 = __ldcg((const float2*)(sin + (size_t)(row0 + rr0) * HID + ccol));
        float2 hp1 = __ldcg((const float2*)(sin + (size_t)(row0 + rr1) * HID + ccol));

        float acc[3][4];
#pragma unroll
        for (int gt = 0; gt < 3; gt++)
#pragma unroll
            for (int q = 0; q < 4; q++) acc[gt][q] = 0.f;

        // ---- K loop: 4 phases of 128 ----
#pragma unroll
        for (int p = 0; p < 4; p++) {
            float* Ab = Afr + (p & 1) * AFRAG_FLOATS;
#pragma unroll
            for (int kc = 0; kc < 4; kc++) {
                int k8buf = kc * 4 + k8f;
                float* d = Ab + (size_t)((k8buf * 2 + mt_w) * 32 + g_w * 4) * 4 + j_w;
                d[0]  = __uint_as_float(f2tf32(ra[kc].x * m_a));
                d[4]  = __uint_as_float(f2tf32(ra[kc].y * m_a));
                d[8]  = __uint_as_float(f2tf32(ra[kc].z * m_a));
                d[12] = __uint_as_float(f2tf32(ra[kc].w * m_a));
            }
            if (p < 3) {
#pragma unroll
                for (int kc = 0; kc < 4; kc++)
                    ra[kc] = __ldcg((const float4*)(arow + (p + 1) * 128 + kc * 32 + c4a));
            }
            __syncthreads();

#pragma unroll
            for (int kk = 0; kk < 16; kk++) {
                float4 v = *(const float4*)(Ab + (size_t)((kk * 2 + mt_c) * 32 + lane) * 4);
                unsigned af[4] = { __float_as_uint(v.x), __float_as_uint(v.y),
                                   __float_as_uint(v.z), __float_as_uint(v.w) };
                int k8 = p * 16 + kk;
#pragma unroll
                for (int gt = 0; gt < 3; gt++) {
                    int nt = gt * 4 + ntb;
                    float2 b2 = *(const float2*)(Bf + (size_t)((nt * 64 + k8) * 32 + lane) * 2);
                    unsigned bf[2] = { __float_as_uint(b2.x), __float_as_uint(b2.y) };
                    mma_tf32(acc[gt], af, bf);
                }
            }
        }

        // ---- fused gate math in registers ----
        {
            float r, z, n;
            r = sigmoidf_(xr0.x + acc[0][0]);
            z = sigmoidf_(xz0.x + acc[1][0]);
            n = tanhf(xn0.x + r * (acc[2][0] + bn2.x));
            float hn0x = (1.f - z) * n + z * (hp0.x * m0);
            r = sigmoidf_(xr0.y + acc[0][1]);
            z = sigmoidf_(xz0.y + acc[1][1]);
            n = tanhf(xn0.y + r * (acc[2][1] + bn2.y));
            float hn0y = (1.f - z) * n + z * (hp0.y * m0);
            r = sigmoidf_(xr1.x + acc[0][2]);
            z = sigmoidf_(xz1.x + acc[1][2]);
            n = tanhf(xn1.x + r * (acc[2][2] + bn2.x));
            float hn1x = (1.f - z) * n + z * (hp1.x * m1);
            r = sigmoidf_(xr1.y + acc[0][3]);
            z = sigmoidf_(xz1.y + acc[1][3]);
            n = tanhf(xn1.y + r * (acc[2][3] + bn2.y));
            float hn1y = (1.f - z) * n + z * (hp1.y * m1);

            float2 o0 = make_float2(hn0x, hn0y);
            float2 o1 = make_float2(hn1x, hn1y);
            *(float2*)(sout + (size_t)(row0 + rr0) * HID + ccol) = o0;
            *(float2*)(sout + (size_t)(row0 + rr1) * HID + ccol) = o1;
            if (t == T_STEPS - 1) {
                *(float2*)(out_state + (size_t)(row0 + rr0) * HID + ccol) = o0;
                *(float2*)(out_state + (size_t)(row0 + rr1) * HID + ccol) = o1;
            }
        }

        if (t < T_STEPS - 1) {
            // prefetch next step's pure inputs BEFORE the barrier spin
            m_a = 1.0f - __ldg(done + (t + 1) * BATCH + row0 + r_a);
            m0  = 1.0f - __ldg(done + (t + 1) * BATCH + row0 + rr0);
            m1  = 1.0f - __ldg(done + (t + 1) * BATCH + row0 + rr1);
            const float* gx0 = g_gx + ((size_t)((t + 1) * BATCH + row0 + rr0)) * (3 * HID);
            const float* gx1 = g_gx + ((size_t)((t + 1) * BATCH + row0 + rr1)) * (3 * HID);
            xr0 = *(const float2*)(gx0 + ccol);
            xz0 = *(const float2*)(gx0 + HID + ccol);
            xn0 = *(const float2*)(gx0 + 2 * HID + ccol);
            xr1 = *(const float2*)(gx1 + ccol);
            xz1 = *(const float2*)(gx1 + HID + ccol);
            xn1 = *(const float2*)(gx1 + 2 * HID + ccol);

            // per-group barrier
            __threadfence();
            __syncthreads();
            if (tid == 0) {
                atomicAdd(&g_barriers[gid][0], 1u);
                unsigned target = (unsigned)BLKS_PER_GROUP * (unsigned)(t + 1);
                while (*(volatile unsigned*)&g_barriers[gid][0] < target) { }
                __threadfence();
            }
            __syncthreads();
        }
    }
}

// ---------------------------------------------------------------------------
// Heads: one warp per row n.
// ---------------------------------------------------------------------------
__global__ __launch_bounds__(256)
void heads_kernel(const int* __restrict__ action,
                  const float* __restrict__ w_actor,
                  const float* __restrict__ b_actor,
                  const float* __restrict__ w_critic,
                  const float* __restrict__ b_critic,
                  float* __restrict__ out)
{
    __shared__ float s_wa[NACT * HID];
    __shared__ float s_wc[HID];
    __shared__ float s_ba[NACT];

    const int tid = threadIdx.x;
    for (int i = tid; i < NACT * HID; i += 256) s_wa[i] = w_actor[i];
    for (int i = tid; i < HID; i += 256) s_wc[i] = w_critic[i];
    if (tid < NACT) s_ba[tid] = b_actor[tid];
    __syncthreads();

    const int warp = tid >> 5;
    const int lane = tid & 31;
    const int n = blockIdx.x * 8 + warp;

    const float* hrow = g_hidden + (size_t)n * HID;
    float h[16];
#pragma unroll
    for (int i = 0; i < 16; i++) h[i] = hrow[lane + 32 * i];

    float l[NACT];
#pragma unroll
    for (int a = 0; a < NACT; a++) {
        float p = 0.f;
        const float* wa = s_wa + a * HID;
#pragma unroll
        for (int i = 0; i < 16; i++) p += h[i] * wa[lane + 32 * i];
#pragma unroll
        for (int o = 16; o > 0; o >>= 1) p += __shfl_xor_sync(0xffffffffu, p, o);
        l[a] = p + s_ba[a];
    }

    float v = 0.f;
#pragma unroll
    for (int i = 0; i < 16; i++) v += h[i] * s_wc[lane + 32 * i];
#pragma unroll
    for (int o = 16; o > 0; o >>= 1) v += __shfl_xor_sync(0xffffffffu, v, o);
    v += b_critic[0];

    float mx = l[0];
#pragma unroll
    for (int a = 1; a < NACT; a++) mx = fmaxf(mx, l[a]);
    float s = 0.f;
#pragma unroll
    for (int a = 0; a < NACT; a++) s += expf(l[a] - mx);
    float lse = mx + logf(s);

    float ent = 0.f;
#pragma unroll
    for (int a = 0; a < NACT; a++) ent += expf(l[a] - lse) * (lse - l[a]);

    int act = action[n];
    float lp = 0.f;
#pragma unroll
    for (int a = 0; a < NACT; a++) lp += (a == act) ? (l[a] - lse) : 0.f;

    if (lane == 0) {
        out[n] = lp;
        out[NTOT + n] = ent;
        out[2 * NTOT + n] = v;
    }
}

// ---------------------------------------------------------------------------
extern "C" void kernel_launch(void* const* d_in, const int* in_sizes, int n_in,
                              void* d_out, int out_size)
{
    const float* x        = (const float*)d_in[0];
    const float* gru_st   = (const float*)d_in[1];
    const float* done     = (const float*)d_in[2];
    const int*   action   = (const int*)  d_in[3];
    const float* w1       = (const float*)d_in[4];
    const float* b1       = (const float*)d_in[5];
    const float* w2       = (const float*)d_in[6];
    const float* b2       = (const float*)d_in[7];
    const float* w_ih     = (const float*)d_in[8];
    const float* w_hh     = (const float*)d_in[9];
    const float* b_ih     = (const float*)d_in[10];
    const float* b_hh     = (const float*)d_in[11];
    const float* w_actor  = (const float*)d_in[12];
    const float* b_actor  = (const float*)d_in[13];
    const float* w_critic = (const float*)d_in[14];
    const float* b_critic = (const float*)d_in[15];
    float* out = (float*)d_out;

    float *h1, *h2, *gx, *bc;
    cudaGetSymbolAddress((void**)&h1, g_h1);
    cudaGetSymbolAddress((void**)&h2, g_h2);
    cudaGetSymbolAddress((void**)&gx, g_gx);
    cudaGetSymbolAddress((void**)&bc, g_bcomb);

    static int attrs_set = 0;
    if (!attrs_set) {
        cudaFuncSetAttribute(gru_scan_kernel,
                             cudaFuncAttributeMaxDynamicSharedMemorySize,
                             SCAN_SMEM_BYTES);
        attrs_set = 1;
    }

    // barriers + combined bias (b_ih + b_hh for r,z gates)
    init_kernel<<<(3 * HID + 255) / 256, 256>>>(b_ih, b_hh);

    // encoder layer 1: (N,512)@(512,256)^T -> h1
    gemm_tf32_kernel<true><<<dim3(ENCD / 64, NTOT / 128), 256>>>(
        x, w1, b1, h1, NTOT, ENCD, OBSD);
    // encoder layer 2: (N,256)@(256,256)^T -> h2
    gemm_tf32_kernel<true><<<dim3(ENCD / 64, NTOT / 128), 256>>>(
        h1, w2, b2, h2, NTOT, ENCD, ENCD);
    // input-side gates (bias = b_ih + b_hh[r,z]): (N,256)@(256,1536)^T -> gx
    gemm_tf32_kernel<false><<<dim3(3 * HID / 64, NTOT / 128), 256>>>(
        h2, w_ih, bc, gx, NTOT, 3 * HID, ENCD);

    // persistent GRU scan
    gru_scan_kernel<<<N_GROUPS * BLKS_PER_GROUP, 256, SCAN_SMEM_BYTES>>>(
        gru_st, w_hh, b_hh, done, out + 3 * NTOT);

    heads_kernel<<<NTOT / 8, 256>>>(action, w_actor, b_actor, w_critic, b_critic, out);
}

// round 8
// speedup vs baseline: 2.5399x; 1.5410x over previous
#include <cuda_runtime.h>
#include <cuda_fp16.h>
#include <math.h>

#define T_STEPS 128
#define BATCH   256
#define OBSD    512
#define ENCD    256
#define HID     512
#define NACT    18
#define NTOT    (T_STEPS * BATCH)   // 32768

#define N_GROUPS 8
#define BLKS_PER_GROUP 16
// scan smem (uints): B frag [12 nt][32 k16][32 lane][2] + A dbl buf [2][8 k16][2 mt][32 lane][4]
#define BF_UINTS (12 * 32 * 32 * 2)          // 24576
#define AF_UINTS (8 * 2 * 32 * 4)            // 2048 per buffer
#define SCAN_SMEM_UINTS (BF_UINTS + 2 * AF_UINTS)
#define SCAN_SMEM_BYTES (SCAN_SMEM_UINTS * 4)   // 114688

// ---------------- scratch (static device globals; no runtime allocation) ----
__device__ float g_h1[(size_t)NTOT * ENCD];
__device__ float g_h2[(size_t)NTOT * ENCD];
__device__ float g_gx[(size_t)NTOT * 3 * HID];
__device__ float g_hidden[(size_t)NTOT * HID];
__device__ float g_bcomb[3 * HID];
__device__ unsigned g_barriers[N_GROUPS][32];   // 128B-padded per-group counters

// ---------------------------------------------------------------------------
__device__ __forceinline__ unsigned pack_h2(float lo, float hi) {
    __half2 h = __float22half2_rn(make_float2(lo, hi));
    return *(unsigned*)&h;
}

__device__ __forceinline__ void mma_f16(float d[4], const unsigned a[4], const unsigned b[2]) {
    asm volatile(
        "mma.sync.aligned.m16n8k16.row.col.f32.f16.f16.f32 "
        "{%0,%1,%2,%3}, {%4,%5,%6,%7}, {%8,%9}, {%0,%1,%2,%3};"
        : "+f"(d[0]), "+f"(d[1]), "+f"(d[2]), "+f"(d[3])
        : "r"(a[0]), "r"(a[1]), "r"(a[2]), "r"(a[3]), "r"(b[0]), "r"(b[1]));
}

__device__ __forceinline__ float sigmoidf_(float x) {
    return 1.f / (1.f + expf(-x));
}

__global__ void init_kernel(const float* __restrict__ b_ih,
                            const float* __restrict__ b_hh)
{
    int i = blockIdx.x * 256 + threadIdx.x;
    if (i < N_GROUPS) g_barriers[i][0] = 0u;
    if (i < 3 * HID)
        g_bcomb[i] = b_ih[i] + ((i < 2 * HID) ? b_hh[i] : 0.f);
}

// ---------------------------------------------------------------------------
// C[M,Nc] = act(A[M,K] @ W[Nc,K]^T + bias) via fp16 mma m16n8k16 (fp32 accum).
// BM=128, BN=64, BK=16, 256 threads (8 warps, 4m x 2n), warptile 32x32.
// smem rows stored as packed half2 (uint): row = 8 data uints + 4 pad.
// ---------------------------------------------------------------------------
template <bool RELU>
__global__ __launch_bounds__(256)
void gemm_f16_kernel(const float* __restrict__ A,
                     const float* __restrict__ W,
                     const float* __restrict__ bias,
                     float* __restrict__ C,
                     int M, int Nc, int K)
{
    __shared__ unsigned As_u[128][12];
    __shared__ unsigned Ws_u[64][12];

    const int tid  = threadIdx.x;
    const int warp = tid >> 5;
    const int lane = tid & 31;
    const int g    = lane >> 2;
    const int tg   = lane & 3;
    const int warp_m = (warp & 3) * 32;
    const int warp_n = (warp >> 2) * 32;
    const int row0 = blockIdx.y * 128;
    const int col0 = blockIdx.x * 64;

    float acc[2][4][4];
#pragma unroll
    for (int i = 0; i < 2; i++)
#pragma unroll
        for (int j = 0; j < 4; j++)
#pragma unroll
            for (int q = 0; q < 4; q++) acc[i][j][q] = 0.f;

    float4 ra[2], rw;
#pragma unroll
    for (int l = 0; l < 2; l++) {
        int i = tid + l * 256;
        ra[l] = *(const float4*)(A + (size_t)(row0 + (i >> 2)) * K + (i & 3) * 4);
    }
    rw = *(const float4*)(W + (size_t)(col0 + (tid >> 2)) * K + (tid & 3) * 4);

    const int nk = K / 16;
    for (int kt = 0; kt < nk; kt++) {
        // ---- store tiles as packed half2 ----
#pragma unroll
        for (int l = 0; l < 2; l++) {
            int i = tid + l * 256;
            int r = i >> 2, cu = (i & 3) * 2;   // uint column
            As_u[r][cu]     = pack_h2(ra[l].x, ra[l].y);
            As_u[r][cu + 1] = pack_h2(ra[l].z, ra[l].w);
        }
        {
            int r = tid >> 2, cu = (tid & 3) * 2;
            Ws_u[r][cu]     = pack_h2(rw.x, rw.y);
            Ws_u[r][cu + 1] = pack_h2(rw.z, rw.w);
        }
        __syncthreads();

        if (kt + 1 < nk) {
            int k0n = (kt + 1) * 16;
#pragma unroll
            for (int l = 0; l < 2; l++) {
                int i = tid + l * 256;
                ra[l] = *(const float4*)(A + (size_t)(row0 + (i >> 2)) * K + k0n + (i & 3) * 4);
            }
            rw = *(const float4*)(W + (size_t)(col0 + (tid >> 2)) * K + k0n + (tid & 3) * 4);
        }

        // ---- one k16 step: 2 m-frags x 4 n-frags ----
        {
            unsigned af[2][4], bf[4][2];
#pragma unroll
            for (int mf = 0; mf < 2; mf++) {
                int br = warp_m + mf * 16;
                af[mf][0] = As_u[br + g][tg];
                af[mf][1] = As_u[br + g + 8][tg];
                af[mf][2] = As_u[br + g][4 + tg];
                af[mf][3] = As_u[br + g + 8][4 + tg];
            }
#pragma unroll
            for (int nf = 0; nf < 4; nf++) {
                int bn = warp_n + nf * 8;
                bf[nf][0] = Ws_u[bn + g][tg];
                bf[nf][1] = Ws_u[bn + g][4 + tg];
            }
#pragma unroll
            for (int mf = 0; mf < 2; mf++)
#pragma unroll
                for (int nf = 0; nf < 4; nf++) mma_f16(acc[mf][nf], af[mf], bf[nf]);
        }
        __syncthreads();
    }

#pragma unroll
    for (int mf = 0; mf < 2; mf++) {
#pragma unroll
        for (int nf = 0; nf < 4; nf++) {
            int r = row0 + warp_m + mf * 16 + g;
            int c = col0 + warp_n + nf * 8 + tg * 2;
            float b0v = bias[c], b1v = bias[c + 1];
            float v0 = acc[mf][nf][0] + b0v;
            float v1 = acc[mf][nf][1] + b1v;
            float v2 = acc[mf][nf][2] + b0v;
            float v3 = acc[mf][nf][3] + b1v;
            if (RELU) {
                v0 = fmaxf(v0, 0.f); v1 = fmaxf(v1, 0.f);
                v2 = fmaxf(v2, 0.f); v3 = fmaxf(v3, 0.f);
            }
            *(float2*)&C[(size_t)r * Nc + c]       = make_float2(v0, v1);
            *(float2*)&C[(size_t)(r + 8) * Nc + c] = make_float2(v2, v3);
        }
    }
}

// ---------------------------------------------------------------------------
// Persistent GRU scan, fp16 mma. 128 blocks = 8 groups x 16 h-col tiles.
// w_hh resident in smem as fp16 mma fragments (98KB). A staged per K-phase
// (128 wide) in fp16 fragment layout. Padded per-group atomic barriers.
// ---------------------------------------------------------------------------
__global__ __launch_bounds__(256)
void gru_scan_kernel(const float* __restrict__ gru_st,
                     const float* __restrict__ w_hh,
                     const float* __restrict__ b_hh,
                     const float* __restrict__ done,
                     float* __restrict__ out_state)
{
    extern __shared__ unsigned smu[];
    unsigned* Bf  = smu;                 // [nt(12)][k16(32)][lane(32)][2]
    unsigned* Afr = smu + BF_UINTS;      // [buf2][k16(8)][mt(2)][lane(32)][4]

    const int tid  = threadIdx.x;
    const int warp = tid >> 5;
    const int lane = tid & 31;
    const int g    = lane >> 2;
    const int tg   = lane & 3;
    const int bid  = blockIdx.x;
    const int col0 = (bid & 15) * 32;     // h-col block
    const int gid  = bid >> 4;            // batch group
    const int row0 = gid * 32;
    const int mt_c = warp & 1;            // consumer m16 tile
    const int ntb  = warp >> 1;           // 0..3: 8-col slot within gate

    // ---- preload w_hh slice into fp16 fragment layout ----
    for (int i = tid; i < 96 * 32; i += 256) {
        int cr   = i >> 5;                // combined row 0..95
        int k16c = i & 31;                // k16 chunk 0..31
        int gate = cr >> 5, lc = cr & 31;
        int nt = cr >> 3, gg = cr & 7;
        const float* wrow = w_hh + (size_t)(gate * HID + col0 + lc) * HID + k16c * 16;
        float4 w0 = *(const float4*)(wrow);
        float4 w1 = *(const float4*)(wrow + 4);
        float4 w2 = *(const float4*)(wrow + 8);
        float4 w3 = *(const float4*)(wrow + 12);
        unsigned u0 = pack_h2(w0.x, w0.y);   // tg0 b0 (k0,k1)
        unsigned u1 = pack_h2(w2.x, w2.y);   // tg0 b1 (k8,k9)
        unsigned u2 = pack_h2(w0.z, w0.w);   // tg1 b0
        unsigned u3 = pack_h2(w2.z, w2.w);   // tg1 b1
        unsigned u4 = pack_h2(w1.x, w1.y);   // tg2 b0
        unsigned u5 = pack_h2(w3.x, w3.y);   // tg2 b1
        unsigned u6 = pack_h2(w1.z, w1.w);   // tg3 b0
        unsigned u7 = pack_h2(w3.z, w3.w);   // tg3 b1
        unsigned* dst = Bf + (size_t)((nt * 32 + k16c) * 32 + gg * 4) * 2;
        *(uint4*)(dst)     = make_uint4(u0, u1, u2, u3);
        *(uint4*)(dst + 4) = make_uint4(u4, u5, u6, u7);
    }

    const int ccol = col0 + ntb * 8 + tg * 2;
    const float2 bn2 = *(const float2*)(b_hh + 2 * HID + ccol);

    // A staging decode (constant over steps)
    const int r_a  = tid >> 3;             // batch row 0..31
    const int c4a  = (tid & 7) * 4;        // k offset within 32
    const int kqo  = c4a >> 4;             // 0 or 1
    const int koff = c4a & 15;             // 0,4,8,12
    const int tg0  = (koff & 7) >> 1;      // 0 or 2
    const int mt_w = r_a >> 4, g_w = r_a & 7, half_w = (r_a >> 3) & 1;
    const int j_w  = half_w + ((koff >> 3) << 1);
    const int rr0  = mt_c * 16 + g;        // gate-math rows
    const int rr1  = rr0 + 8;

    __syncthreads();

    // ---- prefetch step-0 inputs ----
    float m_a = 1.0f - __ldg(done + row0 + r_a);
    float m0  = 1.0f - __ldg(done + row0 + rr0);
    float m1  = 1.0f - __ldg(done + row0 + rr1);
    const float* gx0p = g_gx + ((size_t)(row0 + rr0)) * (3 * HID);
    const float* gx1p = g_gx + ((size_t)(row0 + rr1)) * (3 * HID);
    float2 xr0 = *(const float2*)(gx0p + ccol);
    float2 xz0 = *(const float2*)(gx0p + HID + ccol);
    float2 xn0 = *(const float2*)(gx0p + 2 * HID + ccol);
    float2 xr1 = *(const float2*)(gx1p + ccol);
    float2 xz1 = *(const float2*)(gx1p + HID + ccol);
    float2 xn1 = *(const float2*)(gx1p + 2 * HID + ccol);

    for (int t = 0; t < T_STEPS; t++) {
        const float* sin = (t == 0) ? gru_st
                                    : (g_hidden + (size_t)(t - 1) * BATCH * HID);
        float* sout = g_hidden + (size_t)t * BATCH * HID;

        const float* arow = sin + (size_t)(row0 + r_a) * HID;
        float4 ra[4];
#pragma unroll
        for (int kc = 0; kc < 4; kc++)
            ra[kc] = __ldcg((const float4*)(arow + kc * 32 + c4a));
        float2 hp0 = __ldcg((const float2*)(sin + (size_t)(row0 + rr0) * HID + ccol));
        float2 hp1 = __ldcg((const float2*)(sin + (size_t)(row0 + rr1) * HID + ccol));

        float acc[3][4];
#pragma unroll
        for (int gt = 0; gt < 3; gt++)
#pragma unroll
            for (int q = 0; q < 4; q++) acc[gt][q] = 0.f;

        // ---- K loop: 4 phases of 128 (8 k16 chunks each) ----
#pragma unroll
        for (int p = 0; p < 4; p++) {
            unsigned* Ab = Afr + (p & 1) * AF_UINTS;
#pragma unroll
            for (int kc = 0; kc < 4; kc++) {
                int kq = kc * 2 + kqo;
                unsigned* d = Ab + (size_t)((kq * 2 + mt_w) * 32 + g_w * 4 + tg0) * 4 + j_w;
                d[0] = pack_h2(ra[kc].x * m_a, ra[kc].y * m_a);
                d[4] = pack_h2(ra[kc].z * m_a, ra[kc].w * m_a);
            }
            if (p < 3) {
#pragma unroll
                for (int kc = 0; kc < 4; kc++)
                    ra[kc] = __ldcg((const float4*)(arow + (p + 1) * 128 + kc * 32 + c4a));
            }
            __syncthreads();

#pragma unroll
            for (int kq = 0; kq < 8; kq++) {
                uint4 av = *(const uint4*)(Ab + (size_t)((kq * 2 + mt_c) * 32 + lane) * 4);
                unsigned af[4] = { av.x, av.y, av.z, av.w };
                int k16 = p * 8 + kq;
#pragma unroll
                for (int gt = 0; gt < 3; gt++) {
                    int nt = gt * 4 + ntb;
                    uint2 bv = *(const uint2*)(Bf + (size_t)((nt * 32 + k16) * 32 + lane) * 2);
                    unsigned bf[2] = { bv.x, bv.y };
                    mma_f16(acc[gt], af, bf);
                }
            }
        }

        // ---- fused gate math in registers ----
        {
            float r, z, n;
            r = sigmoidf_(xr0.x + acc[0][0]);
            z = sigmoidf_(xz0.x + acc[1][0]);
            n = tanhf(xn0.x + r * (acc[2][0] + bn2.x));
            float hn0x = (1.f - z) * n + z * (hp0.x * m0);
            r = sigmoidf_(xr0.y + acc[0][1]);
            z = sigmoidf_(xz0.y + acc[1][1]);
            n = tanhf(xn0.y + r * (acc[2][1] + bn2.y));
            float hn0y = (1.f - z) * n + z * (hp0.y * m0);
            r = sigmoidf_(xr1.x + acc[0][2]);
            z = sigmoidf_(xz1.x + acc[1][2]);
            n = tanhf(xn1.x + r * (acc[2][2] + bn2.x));
            float hn1x = (1.f - z) * n + z * (hp1.x * m1);
            r = sigmoidf_(xr1.y + acc[0][3]);
            z = sigmoidf_(xz1.y + acc[1][3]);
            n = tanhf(xn1.y + r * (acc[2][3] + bn2.y));
            float hn1y = (1.f - z) * n + z * (hp1.y * m1);

            float2 o0 = make_float2(hn0x, hn0y);
            float2 o1 = make_float2(hn1x, hn1y);
            *(float2*)(sout + (size_t)(row0 + rr0) * HID + ccol) = o0;
            *(float2*)(sout + (size_t)(row0 + rr1) * HID + ccol) = o1;
            if (t == T_STEPS - 1) {
                *(float2*)(out_state + (size_t)(row0 + rr0) * HID + ccol) = o0;
                *(float2*)(out_state + (size_t)(row0 + rr1) * HID + ccol) = o1;
            }
        }

        if (t < T_STEPS - 1) {
            // prefetch next step's pure inputs BEFORE the barrier spin
            m_a = 1.0f - __ldg(done + (t + 1) * BATCH + row0 + r_a);
            m0  = 1.0f - __ldg(done + (t + 1) * BATCH + row0 + rr0);
            m1  = 1.0f - __ldg(done + (t + 1) * BATCH + row0 + rr1);
            const float* gx0 = g_gx + ((size_t)((t + 1) * BATCH + row0 + rr0)) * (3 * HID);
            const float* gx1 = g_gx + ((size_t)((t + 1) * BATCH + row0 + rr1)) * (3 * HID);
            xr0 = *(const float2*)(gx0 + ccol);
            xz0 = *(const float2*)(gx0 + HID + ccol);
            xn0 = *(const float2*)(gx0 + 2 * HID + ccol);
            xr1 = *(const float2*)(gx1 + ccol);
            xz1 = *(const float2*)(gx1 + HID + ccol);
            xn1 = *(const float2*)(gx1 + 2 * HID + ccol);

            // per-group barrier
            __threadfence();
            __syncthreads();
            if (tid == 0) {
                atomicAdd(&g_barriers[gid][0], 1u);
                unsigned target = (unsigned)BLKS_PER_GROUP * (unsigned)(t + 1);
                while (*(volatile unsigned*)&g_barriers[gid][0] < target) { }
                __threadfence();
            }
            __syncthreads();
        }
    }
}

// ---------------------------------------------------------------------------
// Heads: one warp per row n.
// ---------------------------------------------------------------------------
__global__ __launch_bounds__(256)
void heads_kernel(const int* __restrict__ action,
                  const float* __restrict__ w_actor,
                  const float* __restrict__ b_actor,
                  const float* __restrict__ w_critic,
                  const float* __restrict__ b_critic,
                  float* __restrict__ out)
{
    __shared__ float s_wa[NACT * HID];
    __shared__ float s_wc[HID];
    __shared__ float s_ba[NACT];

    const int tid = threadIdx.x;
    for (int i = tid; i < NACT * HID; i += 256) s_wa[i] = w_actor[i];
    for (int i = tid; i < HID; i += 256) s_wc[i] = w_critic[i];
    if (tid < NACT) s_ba[tid] = b_actor[tid];
    __syncthreads();

    const int warp = tid >> 5;
    const int lane = tid & 31;
    const int n = blockIdx.x * 8 + warp;

    const float* hrow = g_hidden + (size_t)n * HID;
    float h[16];
#pragma unroll
    for (int i = 0; i < 16; i++) h[i] = hrow[lane + 32 * i];

    float l[NACT];
#pragma unroll
    for (int a = 0; a < NACT; a++) {
        float p = 0.f;
        const float* wa = s_wa + a * HID;
#pragma unroll
        for (int i = 0; i < 16; i++) p += h[i] * wa[lane + 32 * i];
#pragma unroll
        for (int o = 16; o > 0; o >>= 1) p += __shfl_xor_sync(0xffffffffu, p, o);
        l[a] = p + s_ba[a];
    }

    float v = 0.f;
#pragma unroll
    for (int i = 0; i < 16; i++) v += h[i] * s_wc[lane + 32 * i];
#pragma unroll
    for (int o = 16; o > 0; o >>= 1) v += __shfl_xor_sync(0xffffffffu, v, o);
    v += b_critic[0];

    float mx = l[0];
#pragma unroll
    for (int a = 1; a < NACT; a++) mx = fmaxf(mx, l[a]);
    float s = 0.f;
#pragma unroll
    for (int a = 0; a < NACT; a++) s += expf(l[a] - mx);
    float lse = mx + logf(s);

    float ent = 0.f;
#pragma unroll
    for (int a = 0; a < NACT; a++) ent += expf(l[a] - lse) * (lse - l[a]);

    int act = action[n];
    float lp = 0.f;
#pragma unroll
    for (int a = 0; a < NACT; a++) lp += (a == act) ? (l[a] - lse) : 0.f;

    if (lane == 0) {
        out[n] = lp;
        out[NTOT + n] = ent;
        out[2 * NTOT + n] = v;
    }
}

// ---------------------------------------------------------------------------
extern "C" void kernel_launch(void* const* d_in, const int* in_sizes, int n_in,
                              void* d_out, int out_size)
{
    const float* x        = (const float*)d_in[0];
    const float* gru_st   = (const float*)d_in[1];
    const float* done     = (const float*)d_in[2];
    const int*   action   = (const int*)  d_in[3];
    const float* w1       = (const float*)d_in[4];
    const float* b1       = (const float*)d_in[5];
    const float* w2       = (const float*)d_in[6];
    const float* b2       = (const float*)d_in[7];
    const float* w_ih     = (const float*)d_in[8];
    const float* w_hh     = (const float*)d_in[9];
    const float* b_ih     = (const float*)d_in[10];
    const float* b_hh     = (const float*)d_in[11];
    const float* w_actor  = (const float*)d_in[12];
    const float* b_actor  = (const float*)d_in[13];
    const float* w_critic = (const float*)d_in[14];
    const float* b_critic = (const float*)d_in[15];
    float* out = (float*)d_out;

    float *h1, *h2, *gx, *bc;
    cudaGetSymbolAddress((void**)&h1, g_h1);
    cudaGetSymbolAddress((void**)&h2, g_h2);
    cudaGetSymbolAddress((void**)&gx, g_gx);
    cudaGetSymbolAddress((void**)&bc, g_bcomb);

    static int attrs_set = 0;
    if (!attrs_set) {
        cudaFuncSetAttribute(gru_scan_kernel,
                             cudaFuncAttributeMaxDynamicSharedMemorySize,
                             SCAN_SMEM_BYTES);
        attrs_set = 1;
    }

    // barriers + combined bias (b_ih + b_hh for r,z gates)
    init_kernel<<<(3 * HID + 255) / 256, 256>>>(b_ih, b_hh);

    // encoder layer 1: (N,512)@(512,256)^T -> h1
    gemm_f16_kernel<true><<<dim3(ENCD / 64, NTOT / 128), 256>>>(
        x, w1, b1, h1, NTOT, ENCD, OBSD);
    // encoder layer 2: (N,256)@(256,256)^T -> h2
    gemm_f16_kernel<true><<<dim3(ENCD / 64, NTOT / 128), 256>>>(
        h1, w2, b2, h2, NTOT, ENCD, ENCD);
    // input-side gates (bias = b_ih + b_hh[r,z]): (N,256)@(256,1536)^T -> gx
    gemm_f16_kernel<false><<<dim3(3 * HID / 64, NTOT / 128), 256>>>(
        h2, w_ih, bc, gx, NTOT, 3 * HID, ENCD);

    // persistent GRU scan
    gru_scan_kernel<<<N_GROUPS * BLKS_PER_GROUP, 256, SCAN_SMEM_BYTES>>>(
        gru_st, w_hh, b_hh, done, out + 3 * NTOT);

    heads_kernel<<<NTOT / 8, 256>>>(action, w_actor, b_actor, w_critic, b_critic, out);
}

// round 9
// speedup vs baseline: 2.6574x; 1.0463x over previous
#include <cuda_runtime.h>
#include <cuda_fp16.h>
#include <math.h>

#define T_STEPS 128
#define BATCH   256
#define OBSD    512
#define ENCD    256
#define HID     512
#define NACT    18
#define NTOT    (T_STEPS * BATCH)   // 32768

#define N_GROUPS 8
#define BLKS_PER_GROUP 16
// scan smem (uints): B frag [12 nt][32 k16][32 lane][2] + A single buf [32 k16][2 mt][32 lane][4]
#define BF_UINTS (12 * 32 * 32 * 2)          // 24576
#define AF_UINTS (32 * 2 * 32 * 4)           // 8192
#define SCAN_SMEM_UINTS (BF_UINTS + AF_UINTS)
#define SCAN_SMEM_BYTES (SCAN_SMEM_UINTS * 4)   // 131072

// ---------------- scratch (static device globals; no runtime allocation) ----
__device__ float g_h1[(size_t)NTOT * ENCD];
__device__ float g_h2[(size_t)NTOT * ENCD];
__device__ float g_gx[(size_t)NTOT * 3 * HID];
__device__ float g_hidden[(size_t)NTOT * HID];
__device__ float g_bcomb[3 * HID];
__device__ unsigned g_barriers[N_GROUPS][32];   // 128B-padded per-group counters

// ---------------------------------------------------------------------------
__device__ __forceinline__ unsigned pack_h2(float lo, float hi) {
    __half2 h = __float22half2_rn(make_float2(lo, hi));
    return *(unsigned*)&h;
}

__device__ __forceinline__ void mma_f16(float d[4], const unsigned a[4], const unsigned b[2]) {
    asm volatile(
        "mma.sync.aligned.m16n8k16.row.col.f32.f16.f16.f32 "
        "{%0,%1,%2,%3}, {%4,%5,%6,%7}, {%8,%9}, {%0,%1,%2,%3};"
        : "+f"(d[0]), "+f"(d[1]), "+f"(d[2]), "+f"(d[3])
        : "r"(a[0]), "r"(a[1]), "r"(a[2]), "r"(a[3]), "r"(b[0]), "r"(b[1]));
}

__device__ __forceinline__ void ldsm_x4(unsigned r[4], unsigned addr) {
    asm volatile(
        "ldmatrix.sync.aligned.m8n8.x4.shared.b16 {%0,%1,%2,%3}, [%4];"
        : "=r"(r[0]), "=r"(r[1]), "=r"(r[2]), "=r"(r[3]) : "r"(addr));
}

__device__ __forceinline__ float sigmoidf_(float x) {
    return 1.f / (1.f + expf(-x));
}

__global__ void init_kernel(const float* __restrict__ b_ih,
                            const float* __restrict__ b_hh)
{
    int i = blockIdx.x * 256 + threadIdx.x;
    if (i < N_GROUPS) g_barriers[i][0] = 0u;
    if (i < 3 * HID)
        g_bcomb[i] = b_ih[i] + ((i < 2 * HID) ? b_hh[i] : 0.f);
}

// ---------------------------------------------------------------------------
// C[M,Nc] = act(A[M,K] @ W[Nc,K]^T + bias) via fp16 mma m16n8k16 (fp32 accum).
// BM=128, BN=64, BK=16, 256 threads (8 warps, 4m x 2n), warptile 32x32.
// ldmatrix.x4 fragment loads; smem double-buffered (1 sync per k16).
// ---------------------------------------------------------------------------
template <bool RELU>
__global__ __launch_bounds__(256)
void gemm_f16_kernel(const float* __restrict__ A,
                     const float* __restrict__ W,
                     const float* __restrict__ bias,
                     float* __restrict__ C,
                     int M, int Nc, int K)
{
    __shared__ unsigned As_u[2][128][12];   // row = 8 data uints + 4 pad (48B stride)
    __shared__ unsigned Ws_u[2][64][12];

    const int tid  = threadIdx.x;
    const int warp = tid >> 5;
    const int lane = tid & 31;
    const int g    = lane >> 2;
    const int tg   = lane & 3;
    const int warp_m = (warp & 3) * 32;
    const int warp_n = (warp >> 2) * 32;
    const int row0 = blockIdx.y * 128;
    const int col0 = blockIdx.x * 64;

    float acc[2][4][4];
#pragma unroll
    for (int i = 0; i < 2; i++)
#pragma unroll
        for (int j = 0; j < 4; j++)
#pragma unroll
            for (int q = 0; q < 4; q++) acc[i][j][q] = 0.f;

    // ldmatrix lane addresses (constant across iterations; buffer offset added in loop)
    const unsigned as_base = (unsigned)__cvta_generic_to_shared(&As_u[0][0][0]);
    const unsigned ws_base = (unsigned)__cvta_generic_to_shared(&Ws_u[0][0][0]);
    const int a_row = warp_m + (lane & 7) + ((lane >> 3) & 1) * 8;
    const unsigned a_off = (unsigned)(a_row * 48 + (lane >> 4) * 16);
    const int w_row = warp_n + (lane & 7) + (lane >> 4) * 8;
    const unsigned w_off = (unsigned)(w_row * 48 + ((lane >> 3) & 1) * 16);

    float4 ra[2], rw;
#pragma unroll
    for (int l = 0; l < 2; l++) {
        int i = tid + l * 256;
        ra[l] = *(const float4*)(A + (size_t)(row0 + (i >> 2)) * K + (i & 3) * 4);
    }
    rw = *(const float4*)(W + (size_t)(col0 + (tid >> 2)) * K + (tid & 3) * 4);

    const int nk = K / 16;
    for (int kt = 0; kt < nk; kt++) {
        const int buf = kt & 1;
        // ---- store tiles as packed half2 (uint2 stores) ----
#pragma unroll
        for (int l = 0; l < 2; l++) {
            int i = tid + l * 256;
            int r = i >> 2, cu = (i & 3) * 2;
            *(uint2*)&As_u[buf][r][cu] =
                make_uint2(pack_h2(ra[l].x, ra[l].y), pack_h2(ra[l].z, ra[l].w));
        }
        {
            int r = tid >> 2, cu = (tid & 3) * 2;
            *(uint2*)&Ws_u[buf][r][cu] =
                make_uint2(pack_h2(rw.x, rw.y), pack_h2(rw.z, rw.w));
        }
        __syncthreads();

        if (kt + 1 < nk) {
            int k0n = (kt + 1) * 16;
#pragma unroll
            for (int l = 0; l < 2; l++) {
                int i = tid + l * 256;
                ra[l] = *(const float4*)(A + (size_t)(row0 + (i >> 2)) * K + k0n + (i & 3) * 4);
            }
            rw = *(const float4*)(W + (size_t)(col0 + (tid >> 2)) * K + k0n + (tid & 3) * 4);
        }

        // ---- fragments via ldmatrix ----
        {
            const unsigned ab = as_base + (unsigned)(buf * 6144) + a_off;
            const unsigned wb = ws_base + (unsigned)(buf * 3072) + w_off;
            unsigned af[2][4], bq[2][4];
            ldsm_x4(af[0], ab);
            ldsm_x4(af[1], ab + 16 * 48);
            ldsm_x4(bq[0], wb);
            ldsm_x4(bq[1], wb + 16 * 48);
            // bq[q] = [nf(2q) b0, nf(2q) b1, nf(2q+1) b0, nf(2q+1) b1]
#pragma unroll
            for (int mf = 0; mf < 2; mf++) {
#pragma unroll
                for (int q = 0; q < 2; q++) {
                    unsigned bf0[2] = { bq[q][0], bq[q][1] };
                    unsigned bf1[2] = { bq[q][2], bq[q][3] };
                    mma_f16(acc[mf][q * 2 + 0], af[mf], bf0);
                    mma_f16(acc[mf][q * 2 + 1], af[mf], bf1);
                }
            }
        }
    }

#pragma unroll
    for (int mf = 0; mf < 2; mf++) {
#pragma unroll
        for (int nf = 0; nf < 4; nf++) {
            int r = row0 + warp_m + mf * 16 + g;
            int c = col0 + warp_n + nf * 8 + tg * 2;
            float b0v = bias[c], b1v = bias[c + 1];
            float v0 = acc[mf][nf][0] + b0v;
            float v1 = acc[mf][nf][1] + b1v;
            float v2 = acc[mf][nf][2] + b0v;
            float v3 = acc[mf][nf][3] + b1v;
            if (RELU) {
                v0 = fmaxf(v0, 0.f); v1 = fmaxf(v1, 0.f);
                v2 = fmaxf(v2, 0.f); v3 = fmaxf(v3, 0.f);
            }
            *(float2*)&C[(size_t)r * Nc + c]       = make_float2(v0, v1);
            *(float2*)&C[(size_t)(r + 8) * Nc + c] = make_float2(v2, v3);
        }
    }
}

// ---------------------------------------------------------------------------
// Persistent GRU scan, fp16 mma. 128 blocks = 8 groups x 16 h-col tiles.
// w_hh resident in smem as fp16 fragments (96KB). A staged once per step
// (full K=512, 32KB, 1 syncthreads). Padded per-group atomic barriers.
// ---------------------------------------------------------------------------
__global__ __launch_bounds__(256)
void gru_scan_kernel(const float* __restrict__ gru_st,
                     const float* __restrict__ w_hh,
                     const float* __restrict__ b_hh,
                     const float* __restrict__ done,
                     float* __restrict__ out_state)
{
    extern __shared__ unsigned smu[];
    unsigned* Bf  = smu;                 // [nt(12)][k16(32)][lane(32)][2]
    unsigned* Afr = smu + BF_UINTS;      // [k16(32)][mt(2)][lane(32)][4]

    const int tid  = threadIdx.x;
    const int warp = tid >> 5;
    const int lane = tid & 31;
    const int g    = lane >> 2;
    const int tg   = lane & 3;
    const int bid  = blockIdx.x;
    const int col0 = (bid & 15) * 32;     // h-col block
    const int gid  = bid >> 4;            // batch group
    const int row0 = gid * 32;
    const int mt_c = warp & 1;            // consumer m16 tile
    const int ntb  = warp >> 1;           // 0..3: 8-col slot within gate

    // ---- preload w_hh slice into fp16 fragment layout ----
    for (int i = tid; i < 96 * 32; i += 256) {
        int cr   = i >> 5;                // combined row 0..95
        int k16c = i & 31;                // k16 chunk 0..31
        int gate = cr >> 5, lc = cr & 31;
        int nt = cr >> 3, gg = cr & 7;
        const float* wrow = w_hh + (size_t)(gate * HID + col0 + lc) * HID + k16c * 16;
        float4 w0 = *(const float4*)(wrow);
        float4 w1 = *(const float4*)(wrow + 4);
        float4 w2 = *(const float4*)(wrow + 8);
        float4 w3 = *(const float4*)(wrow + 12);
        unsigned u0 = pack_h2(w0.x, w0.y);
        unsigned u1 = pack_h2(w2.x, w2.y);
        unsigned u2 = pack_h2(w0.z, w0.w);
        unsigned u3 = pack_h2(w2.z, w2.w);
        unsigned u4 = pack_h2(w1.x, w1.y);
        unsigned u5 = pack_h2(w3.x, w3.y);
        unsigned u6 = pack_h2(w1.z, w1.w);
        unsigned u7 = pack_h2(w3.z, w3.w);
        unsigned* dst = Bf + (size_t)((nt * 32 + k16c) * 32 + gg * 4) * 2;
        *(uint4*)(dst)     = make_uint4(u0, u1, u2, u3);
        *(uint4*)(dst + 4) = make_uint4(u4, u5, u6, u7);
    }

    const int ccol = col0 + ntb * 8 + tg * 2;
    const float2 bn2 = *(const float2*)(b_hh + 2 * HID + ccol);

    // A staging decode (constant over steps)
    const int r_a  = tid >> 3;             // batch row 0..31
    const int c4a  = (tid & 7) * 4;        // k offset within 32
    const int kqo  = c4a >> 4;             // 0 or 1
    const int koff = c4a & 15;
    const int tg0  = (koff & 7) >> 1;
    const int mt_w = r_a >> 4, g_w = r_a & 7, half_w = (r_a >> 3) & 1;
    const int j_w  = half_w + ((koff >> 3) << 1);
    const int rr0  = mt_c * 16 + g;        // gate-math rows
    const int rr1  = rr0 + 8;

    __syncthreads();

    // ---- prefetch step-0 inputs ----
    float m_a = 1.0f - __ldg(done + row0 + r_a);
    float m0  = 1.0f - __ldg(done + row0 + rr0);
    float m1  = 1.0f - __ldg(done + row0 + rr1);
    const float* gx0p = g_gx + ((size_t)(row0 + rr0)) * (3 * HID);
    const float* gx1p = g_gx + ((size_t)(row0 + rr1)) * (3 * HID);
    float2 xr0 = *(const float2*)(gx0p + ccol);
    float2 xz0 = *(const float2*)(gx0p + HID + ccol);
    float2 xn0 = *(const float2*)(gx0p + 2 * HID + ccol);
    float2 xr1 = *(const float2*)(gx1p + ccol);
    float2 xz1 = *(const float2*)(gx1p + HID + ccol);
    float2 xn1 = *(const float2*)(gx1p + 2 * HID + ccol);

    for (int t = 0; t < T_STEPS; t++) {
        const float* sin = (t == 0) ? gru_st
                                    : (g_hidden + (size_t)(t - 1) * BATCH * HID);
        float* sout = g_hidden + (size_t)t * BATCH * HID;

        // ---- load full h_prev rows (16 float4/thread, high MLP) ----
        const float* arow = sin + (size_t)(row0 + r_a) * HID;
        float4 ra[16];
#pragma unroll
        for (int kc = 0; kc < 16; kc++)
            ra[kc] = __ldcg((const float4*)(arow + kc * 32 + c4a));
        float2 hp0 = __ldcg((const float2*)(sin + (size_t)(row0 + rr0) * HID + ccol));
        float2 hp1 = __ldcg((const float2*)(sin + (size_t)(row0 + rr1) * HID + ccol));

        // ---- stage all K=512 into fragment layout, one sync ----
#pragma unroll
        for (int kc = 0; kc < 16; kc++) {
            int kq = kc * 2 + kqo;
            unsigned* d = Afr + (size_t)((kq * 2 + mt_w) * 32 + g_w * 4 + tg0) * 4 + j_w;
            d[0] = pack_h2(ra[kc].x * m_a, ra[kc].y * m_a);
            d[4] = pack_h2(ra[kc].z * m_a, ra[kc].w * m_a);
        }
        __syncthreads();

        float acc[3][4];
#pragma unroll
        for (int gt = 0; gt < 3; gt++)
#pragma unroll
            for (int q = 0; q < 4; q++) acc[gt][q] = 0.f;

        // ---- 32 k16 chunks of mma ----
#pragma unroll 8
        for (int kq = 0; kq < 32; kq++) {
            uint4 av = *(const uint4*)(Afr + (size_t)((kq * 2 + mt_c) * 32 + lane) * 4);
            unsigned af[4] = { av.x, av.y, av.z, av.w };
#pragma unroll
            for (int gt = 0; gt < 3; gt++) {
                int nt = gt * 4 + ntb;
                uint2 bv = *(const uint2*)(Bf + (size_t)((nt * 32 + kq) * 32 + lane) * 2);
                unsigned bf[2] = { bv.x, bv.y };
                mma_f16(acc[gt], af, bf);
            }
        }

        // ---- fused gate math in registers ----
        {
            float r, z, n;
            r = sigmoidf_(xr0.x + acc[0][0]);
            z = sigmoidf_(xz0.x + acc[1][0]);
            n = tanhf(xn0.x + r * (acc[2][0] + bn2.x));
            float hn0x = (1.f - z) * n + z * (hp0.x * m0);
            r = sigmoidf_(xr0.y + acc[0][1]);
            z = sigmoidf_(xz0.y + acc[1][1]);
            n = tanhf(xn0.y + r * (acc[2][1] + bn2.y));
            float hn0y = (1.f - z) * n + z * (hp0.y * m0);
            r = sigmoidf_(xr1.x + acc[0][2]);
            z = sigmoidf_(xz1.x + acc[1][2]);
            n = tanhf(xn1.x + r * (acc[2][2] + bn2.x));
            float hn1x = (1.f - z) * n + z * (hp1.x * m1);
            r = sigmoidf_(xr1.y + acc[0][3]);
            z = sigmoidf_(xz1.y + acc[1][3]);
            n = tanhf(xn1.y + r * (acc[2][3] + bn2.y));
            float hn1y = (1.f - z) * n + z * (hp1.y * m1);

            float2 o0 = make_float2(hn0x, hn0y);
            float2 o1 = make_float2(hn1x, hn1y);
            *(float2*)(sout + (size_t)(row0 + rr0) * HID + ccol) = o0;
            *(float2*)(sout + (size_t)(row0 + rr1) * HID + ccol) = o1;
            if (t == T_STEPS - 1) {
                *(float2*)(out_state + (size_t)(row0 + rr0) * HID + ccol) = o0;
                *(float2*)(out_state + (size_t)(row0 + rr1) * HID + ccol) = o1;
            }
        }

        if (t < T_STEPS - 1) {
            // prefetch next step's pure inputs BEFORE the barrier spin
            m_a = 1.0f - __ldg(done + (t + 1) * BATCH + row0 + r_a);
            m0  = 1.0f - __ldg(done + (t + 1) * BATCH + row0 + rr0);
            m1  = 1.0f - __ldg(done + (t + 1) * BATCH + row0 + rr1);
            const float* gx0 = g_gx + ((size_t)((t + 1) * BATCH + row0 + rr0)) * (3 * HID);
            const float* gx1 = g_gx + ((size_t)((t + 1) * BATCH + row0 + rr1)) * (3 * HID);
            xr0 = *(const float2*)(gx0 + ccol);
            xz0 = *(const float2*)(gx0 + HID + ccol);
            xn0 = *(const float2*)(gx0 + 2 * HID + ccol);
            xr1 = *(const float2*)(gx1 + ccol);
            xz1 = *(const float2*)(gx1 + HID + ccol);
            xn1 = *(const float2*)(gx1 + 2 * HID + ccol);

            // per-group barrier
            __threadfence();
            __syncthreads();
            if (tid == 0) {
                atomicAdd(&g_barriers[gid][0], 1u);
                unsigned target = (unsigned)BLKS_PER_GROUP * (unsigned)(t + 1);
                while (*(volatile unsigned*)&g_barriers[gid][0] < target) { }
                __threadfence();
            }
            __syncthreads();
        }
    }
}

// ---------------------------------------------------------------------------
// Heads: one warp per row n.
// ---------------------------------------------------------------------------
__global__ __launch_bounds__(256)
void heads_kernel(const int* __restrict__ action,
                  const float* __restrict__ w_actor,
                  const float* __restrict__ b_actor,
                  const float* __restrict__ w_critic,
                  const float* __restrict__ b_critic,
                  float* __restrict__ out)
{
    __shared__ float s_wa[NACT * HID];
    __shared__ float s_wc[HID];
    __shared__ float s_ba[NACT];

    const int tid = threadIdx.x;
    for (int i = tid; i < NACT * HID; i += 256) s_wa[i] = w_actor[i];
    for (int i = tid; i < HID; i += 256) s_wc[i] = w_critic[i];
    if (tid < NACT) s_ba[tid] = b_actor[tid];
    __syncthreads();

    const int warp = tid >> 5;
    const int lane = tid & 31;
    const int n = blockIdx.x * 8 + warp;

    const float* hrow = g_hidden + (size_t)n * HID;
    float h[16];
#pragma unroll
    for (int i = 0; i < 16; i++) h[i] = hrow[lane + 32 * i];

    float l[NACT];
#pragma unroll
    for (int a = 0; a < NACT; a++) {
        float p = 0.f;
        const float* wa = s_wa + a * HID;
#pragma unroll
        for (int i = 0; i < 16; i++) p += h[i] * wa[lane + 32 * i];
#pragma unroll
        for (int o = 16; o > 0; o >>= 1) p += __shfl_xor_sync(0xffffffffu, p, o);
        l[a] = p + s_ba[a];
    }

    float v = 0.f;
#pragma unroll
    for (int i = 0; i < 16; i++) v += h[i] * s_wc[lane + 32 * i];
#pragma unroll
    for (int o = 16; o > 0; o >>= 1) v += __shfl_xor_sync(0xffffffffu, v, o);
    v += b_critic[0];

    float mx = l[0];
#pragma unroll
    for (int a = 1; a < NACT; a++) mx = fmaxf(mx, l[a]);
    float s = 0.f;
#pragma unroll
    for (int a = 0; a < NACT; a++) s += expf(l[a] - mx);
    float lse = mx + logf(s);

    float ent = 0.f;
#pragma unroll
    for (int a = 0; a < NACT; a++) ent += expf(l[a] - lse) * (lse - l[a]);

    int act = action[n];
    float lp = 0.f;
#pragma unroll
    for (int a = 0; a < NACT; a++) lp += (a == act) ? (l[a] - lse) : 0.f;

    if (lane == 0) {
        out[n] = lp;
        out[NTOT + n] = ent;
        out[2 * NTOT + n] = v;
    }
}

// ---------------------------------------------------------------------------
extern "C" void kernel_launch(void* const* d_in, const int* in_sizes, int n_in,
                              void* d_out, int out_size)
{
    const float* x        = (const float*)d_in[0];
    const float* gru_st   = (const float*)d_in[1];
    const float* done     = (const float*)d_in[2];
    const int*   action   = (const int*)  d_in[3];
    const float* w1       = (const float*)d_in[4];
    const float* b1       = (const float*)d_in[5];
    const float* w2       = (const float*)d_in[6];
    const float* b2       = (const float*)d_in[7];
    const float* w_ih     = (const float*)d_in[8];
    const float* w_hh     = (const float*)d_in[9];
    const float* b_ih     = (const float*)d_in[10];
    const float* b_hh     = (const float*)d_in[11];
    const float* w_actor  = (const float*)d_in[12];
    const float* b_actor  = (const float*)d_in[13];
    const float* w_critic = (const float*)d_in[14];
    const float* b_critic = (const float*)d_in[15];
    float* out = (float*)d_out;

    float *h1, *h2, *gx, *bc;
    cudaGetSymbolAddress((void**)&h1, g_h1);
    cudaGetSymbolAddress((void**)&h2, g_h2);
    cudaGetSymbolAddress((void**)&gx, g_gx);
    cudaGetSymbolAddress((void**)&bc, g_bcomb);

    static int attrs_set = 0;
    if (!attrs_set) {
        cudaFuncSetAttribute(gru_scan_kernel,
                             cudaFuncAttributeMaxDynamicSharedMemorySize,
                             SCAN_SMEM_BYTES);
        attrs_set = 1;
    }

    // barriers + combined bias (b_ih + b_hh for r,z gates)
    init_kernel<<<(3 * HID + 255) / 256, 256>>>(b_ih, b_hh);

    // encoder layer 1: (N,512)@(512,256)^T -> h1
    gemm_f16_kernel<true><<<dim3(ENCD / 64, NTOT / 128), 256>>>(
        x, w1, b1, h1, NTOT, ENCD, OBSD);
    // encoder layer 2: (N,256)@(256,256)^T -> h2
    gemm_f16_kernel<true><<<dim3(ENCD / 64, NTOT / 128), 256>>>(
        h1, w2, b2, h2, NTOT, ENCD, ENCD);
    // input-side gates (bias = b_ih + b_hh[r,z]): (N,256)@(256,1536)^T -> gx
    gemm_f16_kernel<false><<<dim3(3 * HID / 64, NTOT / 128), 256>>>(
        h2, w_ih, bc, gx, NTOT, 3 * HID, ENCD);

    // persistent GRU scan
    gru_scan_kernel<<<N_GROUPS * BLKS_PER_GROUP, 256, SCAN_SMEM_BYTES>>>(
        gru_st, w_hh, b_hh, done, out + 3 * NTOT);

    heads_kernel<<<NTOT / 8, 256>>>(action, w_actor, b_actor, w_critic, b_critic, out);
}

// round 12
// speedup vs baseline: 2.8315x; 1.0655x over previous
#include <cuda_runtime.h>
#include <cuda_fp16.h>
#include <cstdint>
#include <math.h>

#define T_STEPS 128
#define BATCH   256
#define OBSD    512
#define ENCD    256
#define HID     512
#define NACT    18
#define NTOT    (T_STEPS * BATCH)   // 32768

#define N_GROUPS 8
#define BLKS_PER_GROUP 16
// scan smem (uints): B frag [12 nt][32 k16][32 lane][2] + A single buf [32 k16][2 mt][32 lane][4]
#define BF_UINTS (12 * 32 * 32 * 2)          // 24576
#define AF_UINTS (32 * 2 * 32 * 4)           // 8192
#define SCAN_SMEM_UINTS (BF_UINTS + AF_UINTS)
#define SCAN_SMEM_BYTES (SCAN_SMEM_UINTS * 4)   // 131072

// ---------------- scratch (static device globals; no runtime allocation) ----
__device__ float g_h1[(size_t)NTOT * ENCD];
__device__ float g_h2[(size_t)NTOT * ENCD];
__device__ float g_gx[(size_t)NTOT * 3 * HID];
__device__ float g_hidden[(size_t)NTOT * HID];
__device__ float g_bcomb[3 * HID];
__device__ unsigned g_barriers[N_GROUPS][32];   // 128B-padded per-group counters

// ---------------------------------------------------------------------------
__device__ __forceinline__ unsigned pack_h2(float lo, float hi) {
    __half2 h = __float22half2_rn(make_float2(lo, hi));
    return *(unsigned*)&h;
}

__device__ __forceinline__ void mma_f16(float d[4], const unsigned a[4], const unsigned b[2]) {
    asm volatile(
        "mma.sync.aligned.m16n8k16.row.col.f32.f16.f16.f32 "
        "{%0,%1,%2,%3}, {%4,%5,%6,%7}, {%8,%9}, {%0,%1,%2,%3};"
        : "+f"(d[0]), "+f"(d[1]), "+f"(d[2]), "+f"(d[3])
        : "r"(a[0]), "r"(a[1]), "r"(a[2]), "r"(a[3]), "r"(b[0]), "r"(b[1]));
}

__device__ __forceinline__ void ldsm_x4(unsigned r[4], unsigned addr) {
    asm volatile(
        "ldmatrix.sync.aligned.m8n8.x4.shared.b16 {%0,%1,%2,%3}, [%4];"
        : "=r"(r[0]), "=r"(r[1]), "=r"(r[2]), "=r"(r[3]) : "r"(addr));
}

__device__ __forceinline__ float sigmoidf_(float x) {
    return 1.f / (1.f + expf(-x));
}

__global__ void init_kernel(const float* __restrict__ b_ih,
                            const float* __restrict__ b_hh)
{
    int i = blockIdx.x * 256 + threadIdx.x;
    if (i < N_GROUPS) g_barriers[i][0] = 0u;
    if (i < 3 * HID)
        g_bcomb[i] = b_ih[i] + ((i < 2 * HID) ? b_hh[i] : 0.f);
}

// ---------------------------------------------------------------------------
// C[M,Nc] = act(A[M,K] @ W[Nc,K]^T + bias) via fp16 mma m16n8k16 (fp32 accum).
// BM=128, BN=128, BK=16, 256 threads (8 warps, 2m x 4n), warptile 64x32.
// ldmatrix.x4 fragment loads; smem double-buffered (1 sync per k16).
// ---------------------------------------------------------------------------
template <bool RELU>
__global__ __launch_bounds__(256)
void gemm_f16_kernel(const float* __restrict__ A,
                     const float* __restrict__ W,
                     const float* __restrict__ bias,
                     float* __restrict__ C,
                     int M, int Nc, int K)
{
    __shared__ unsigned As_u[2][128][12];   // row = 8 data uints + 4 pad (48B stride)
    __shared__ unsigned Ws_u[2][128][12];

    const int tid  = threadIdx.x;
    const int warp = tid >> 5;
    const int lane = tid & 31;
    const int g    = lane >> 2;
    const int tg   = lane & 3;
    const int warp_m = (warp & 1) * 64;    // 2 m-warps, 64 rows each
    const int warp_n = (warp >> 1) * 32;   // 4 n-warps, 32 cols each
    const int row0 = blockIdx.y * 128;
    const int col0 = blockIdx.x * 128;

    float acc[4][4][4];
#pragma unroll
    for (int i = 0; i < 4; i++)
#pragma unroll
        for (int j = 0; j < 4; j++)
#pragma unroll
            for (int q = 0; q < 4; q++) acc[i][j][q] = 0.f;

    const unsigned as_base = (unsigned)__cvta_generic_to_shared(&As_u[0][0][0]);
    const unsigned ws_base = (unsigned)__cvta_generic_to_shared(&Ws_u[0][0][0]);
    const unsigned a_off = (unsigned)((warp_m + (lane & 7) + ((lane >> 3) & 1) * 8) * 48
                                      + (lane >> 4) * 16);
    const unsigned w_off = (unsigned)((warp_n + (lane & 7) + (lane >> 4) * 8) * 48
                                      + ((lane >> 3) & 1) * 16);

    float4 ra[2], rw[2];
#pragma unroll
    for (int l = 0; l < 2; l++) {
        int i = tid + l * 256;
        ra[l] = *(const float4*)(A + (size_t)(row0 + (i >> 2)) * K + (i & 3) * 4);
        rw[l] = *(const float4*)(W + (size_t)(col0 + (i >> 2)) * K + (i & 3) * 4);
    }

    const int nk = K / 16;
    for (int kt = 0; kt < nk; kt++) {
        const int buf = kt & 1;
        // ---- store tiles as packed half2 (uint2 stores) ----
#pragma unroll
        for (int l = 0; l < 2; l++) {
            int i = tid + l * 256;
            int r = i >> 2, cu = (i & 3) * 2;
            *(uint2*)&As_u[buf][r][cu] =
                make_uint2(pack_h2(ra[l].x, ra[l].y), pack_h2(ra[l].z, ra[l].w));
            *(uint2*)&Ws_u[buf][r][cu] =
                make_uint2(pack_h2(rw[l].x, rw[l].y), pack_h2(rw[l].z, rw[l].w));
        }
        __syncthreads();

        if (kt + 1 < nk) {
            int k0n = (kt + 1) * 16;
#pragma unroll
            for (int l = 0; l < 2; l++) {
                int i = tid + l * 256;
                ra[l] = *(const float4*)(A + (size_t)(row0 + (i >> 2)) * K + k0n + (i & 3) * 4);
                rw[l] = *(const float4*)(W + (size_t)(col0 + (i >> 2)) * K + k0n + (i & 3) * 4);
            }
        }

        // ---- fragments via ldmatrix: 4 A (m16 each) + 2 W (2 n8 each) ----
        {
            const unsigned ab = as_base + (unsigned)(buf * 6144) + a_off;
            const unsigned wb = ws_base + (unsigned)(buf * 6144) + w_off;
            unsigned af[4][4], bq[2][4];
#pragma unroll
            for (int mf = 0; mf < 4; mf++) ldsm_x4(af[mf], ab + mf * 768);
#pragma unroll
            for (int q = 0; q < 2; q++) ldsm_x4(bq[q], wb + q * 768);
#pragma unroll
            for (int mf = 0; mf < 4; mf++) {
#pragma unroll
                for (int q = 0; q < 2; q++) {
                    unsigned bf0[2] = { bq[q][0], bq[q][1] };
                    unsigned bf1[2] = { bq[q][2], bq[q][3] };
                    mma_f16(acc[mf][q * 2 + 0], af[mf], bf0);
                    mma_f16(acc[mf][q * 2 + 1], af[mf], bf1);
                }
            }
        }
    }

#pragma unroll
    for (int mf = 0; mf < 4; mf++) {
#pragma unroll
        for (int nf = 0; nf < 4; nf++) {
            int r = row0 + warp_m + mf * 16 + g;
            int c = col0 + warp_n + nf * 8 + tg * 2;
            float b0v = bias[c], b1v = bias[c + 1];
            float v0 = acc[mf][nf][0] + b0v;
            float v1 = acc[mf][nf][1] + b1v;
            float v2 = acc[mf][nf][2] + b0v;
            float v3 = acc[mf][nf][3] + b1v;
            if (RELU) {
                v0 = fmaxf(v0, 0.f); v1 = fmaxf(v1, 0.f);
                v2 = fmaxf(v2, 0.f); v3 = fmaxf(v3, 0.f);
            }
            *(float2*)&C[(size_t)r * Nc + c]       = make_float2(v0, v1);
            *(float2*)&C[(size_t)(r + 8) * Nc + c] = make_float2(v2, v3);
        }
    }
}

// ---------------------------------------------------------------------------
// Persistent GRU scan, fp16 mma (R9, best measured). 128 blocks = 8 groups x 16 tiles.
// ---------------------------------------------------------------------------
__global__ __launch_bounds__(256)
void gru_scan_kernel(const float* __restrict__ gru_st,
                     const float* __restrict__ w_hh,
                     const float* __restrict__ b_hh,
                     const float* __restrict__ done,
                     float* __restrict__ out_state)
{
    extern __shared__ unsigned smu[];
    unsigned* Bf  = smu;                 // [nt(12)][k16(32)][lane(32)][2]
    unsigned* Afr = smu + BF_UINTS;      // [k16(32)][mt(2)][lane(32)][4]

    const int tid  = threadIdx.x;
    const int warp = tid >> 5;
    const int lane = tid & 31;
    const int g    = lane >> 2;
    const int tg   = lane & 3;
    const int bid  = blockIdx.x;
    const int col0 = (bid & 15) * 32;     // h-col block
    const int gid  = bid >> 4;            // batch group
    const int row0 = gid * 32;
    const int mt_c = warp & 1;            // consumer m16 tile
    const int ntb  = warp >> 1;           // 0..3: 8-col slot within gate

    // ---- preload w_hh slice into fp16 fragment layout ----
    for (int i = tid; i < 96 * 32; i += 256) {
        int cr   = i >> 5;
        int k16c = i & 31;
        int gate = cr >> 5, lc = cr & 31;
        int nt = cr >> 3, gg = cr & 7;
        const float* wrow = w_hh + (size_t)(gate * HID + col0 + lc) * HID + k16c * 16;
        float4 w0 = *(const float4*)(wrow);
        float4 w1 = *(const float4*)(wrow + 4);
        float4 w2 = *(const float4*)(wrow + 8);
        float4 w3 = *(const float4*)(wrow + 12);
        unsigned u0 = pack_h2(w0.x, w0.y);
        unsigned u1 = pack_h2(w2.x, w2.y);
        unsigned u2 = pack_h2(w0.z, w0.w);
        unsigned u3 = pack_h2(w2.z, w2.w);
        unsigned u4 = pack_h2(w1.x, w1.y);
        unsigned u5 = pack_h2(w3.x, w3.y);
        unsigned u6 = pack_h2(w1.z, w1.w);
        unsigned u7 = pack_h2(w3.z, w3.w);
        unsigned* dst = Bf + (size_t)((nt * 32 + k16c) * 32 + gg * 4) * 2;
        *(uint4*)(dst)     = make_uint4(u0, u1, u2, u3);
        *(uint4*)(dst + 4) = make_uint4(u4, u5, u6, u7);
    }

    const int ccol = col0 + ntb * 8 + tg * 2;
    const float2 bn2 = *(const float2*)(b_hh + 2 * HID + ccol);

    const int r_a  = tid >> 3;
    const int c4a  = (tid & 7) * 4;
    const int kqo  = c4a >> 4;
    const int koff = c4a & 15;
    const int tg0  = (koff & 7) >> 1;
    const int mt_w = r_a >> 4, g_w = r_a & 7, half_w = (r_a >> 3) & 1;
    const int j_w  = half_w + ((koff >> 3) << 1);
    const int rr0  = mt_c * 16 + g;
    const int rr1  = rr0 + 8;

    __syncthreads();

    float m_a = 1.0f - __ldg(done + row0 + r_a);
    float m0  = 1.0f - __ldg(done + row0 + rr0);
    float m1  = 1.0f - __ldg(done + row0 + rr1);
    const float* gx0p = g_gx + ((size_t)(row0 + rr0)) * (3 * HID);
    const float* gx1p = g_gx + ((size_t)(row0 + rr1)) * (3 * HID);
    float2 xr0 = *(const float2*)(gx0p + ccol);
    float2 xz0 = *(const float2*)(gx0p + HID + ccol);
    float2 xn0 = *(const float2*)(gx0p + 2 * HID + ccol);
    float2 xr1 = *(const float2*)(gx1p + ccol);
    float2 xz1 = *(const float2*)(gx1p + HID + ccol);
    float2 xn1 = *(const float2*)(gx1p + 2 * HID + ccol);

    for (int t = 0; t < T_STEPS; t++) {
        const float* sin = (t == 0) ? gru_st
                                    : (g_hidden + (size_t)(t - 1) * BATCH * HID);
        float* sout = g_hidden + (size_t)t * BATCH * HID;

        const float* arow = sin + (size_t)(row0 + r_a) * HID;
        float4 ra[16];
#pragma unroll
        for (int kc = 0; kc < 16; kc++)
            ra[kc] = __ldcg((const float4*)(arow + kc * 32 + c4a));
        float2 hp0 = __ldcg((const float2*)(sin + (size_t)(row0 + rr0) * HID + ccol));
        float2 hp1 = __ldcg((const float2*)(sin + (size_t)(row0 + rr1) * HID + ccol));

#pragma unroll
        for (int kc = 0; kc < 16; kc++) {
            int kq = kc * 2 + kqo;
            unsigned* d = Afr + (size_t)((kq * 2 + mt_w) * 32 + g_w * 4 + tg0) * 4 + j_w;
            d[0] = pack_h2(ra[kc].x * m_a, ra[kc].y * m_a);
            d[4] = pack_h2(ra[kc].z * m_a, ra[kc].w * m_a);
        }
        __syncthreads();

        float acc[3][4];
#pragma unroll
        for (int gt = 0; gt < 3; gt++)
#pragma unroll
            for (int q = 0; q < 4; q++) acc[gt][q] = 0.f;

#pragma unroll 8
        for (int kq = 0; kq < 32; kq++) {
            uint4 av = *(const uint4*)(Afr + (size_t)((kq * 2 + mt_c) * 32 + lane) * 4);
            unsigned af[4] = { av.x, av.y, av.z, av.w };
#pragma unroll
            for (int gt = 0; gt < 3; gt++) {
                int nt = gt * 4 + ntb;
                uint2 bv = *(const uint2*)(Bf + (size_t)((nt * 32 + kq) * 32 + lane) * 2);
                unsigned bf[2] = { bv.x, bv.y };
                mma_f16(acc[gt], af, bf);
            }
        }

        {
            float r, z, n;
            r = sigmoidf_(xr0.x + acc[0][0]);
            z = sigmoidf_(xz0.x + acc[1][0]);
            n = tanhf(xn0.x + r * (acc[2][0] + bn2.x));
            float hn0x = (1.f - z) * n + z * (hp0.x * m0);
            r = sigmoidf_(xr0.y + acc[0][1]);
            z = sigmoidf_(xz0.y + acc[1][1]);
            n = tanhf(xn0.y + r * (acc[2][1] + bn2.y));
            float hn0y = (1.f - z) * n + z * (hp0.y * m0);
            r = sigmoidf_(xr1.x + acc[0][2]);
            z = sigmoidf_(xz1.x + acc[1][2]);
            n = tanhf(xn1.x + r * (acc[2][2] + bn2.x));
            float hn1x = (1.f - z) * n + z * (hp1.x * m1);
            r = sigmoidf_(xr1.y + acc[0][3]);
            z = sigmoidf_(xz1.y + acc[1][3]);
            n = tanhf(xn1.y + r * (acc[2][3] + bn2.y));
            float hn1y = (1.f - z) * n + z * (hp1.y * m1);

            float2 o0 = make_float2(hn0x, hn0y);
            float2 o1 = make_float2(hn1x, hn1y);
            *(float2*)(sout + (size_t)(row0 + rr0) * HID + ccol) = o0;
            *(float2*)(sout + (size_t)(row0 + rr1) * HID + ccol) = o1;
            if (t == T_STEPS - 1) {
                *(float2*)(out_state + (size_t)(row0 + rr0) * HID + ccol) = o0;
                *(float2*)(out_state + (size_t)(row0 + rr1) * HID + ccol) = o1;
            }
        }

        if (t < T_STEPS - 1) {
            m_a = 1.0f - __ldg(done + (t + 1) * BATCH + row0 + r_a);
            m0  = 1.0f - __ldg(done + (t + 1) * BATCH + row0 + rr0);
            m1  = 1.0f - __ldg(done + (t + 1) * BATCH + row0 + rr1);
            const float* gx0 = g_gx + ((size_t)((t + 1) * BATCH + row0 + rr0)) * (3 * HID);
            const float* gx1 = g_gx + ((size_t)((t + 1) * BATCH + row0 + rr1)) * (3 * HID);
            xr0 = *(const float2*)(gx0 + ccol);
            xz0 = *(const float2*)(gx0 + HID + ccol);
            xn0 = *(const float2*)(gx0 + 2 * HID + ccol);
            xr1 = *(const float2*)(gx1 + ccol);
            xz1 = *(const float2*)(gx1 + HID + ccol);
            xn1 = *(const float2*)(gx1 + 2 * HID + ccol);

            __threadfence();
            __syncthreads();
            if (tid == 0) {
                atomicAdd(&g_barriers[gid][0], 1u);
                unsigned target = (unsigned)BLKS_PER_GROUP * (unsigned)(t + 1);
                while (*(volatile unsigned*)&g_barriers[gid][0] < target) { }
                __threadfence();
            }
            __syncthreads();
        }
    }
}

// ---------------------------------------------------------------------------
// Heads: one warp per row n.
// ---------------------------------------------------------------------------
__global__ __launch_bounds__(256)
void heads_kernel(const int* __restrict__ action,
                  const float* __restrict__ w_actor,
                  const float* __restrict__ b_actor,
                  const float* __restrict__ w_critic,
                  const float* __restrict__ b_critic,
                  float* __restrict__ out)
{
    __shared__ float s_wa[NACT * HID];
    __shared__ float s_wc[HID];
    __shared__ float s_ba[NACT];

    const int tid = threadIdx.x;
    for (int i = tid; i < NACT * HID; i += 256) s_wa[i] = w_actor[i];
    for (int i = tid; i < HID; i += 256) s_wc[i] = w_critic[i];
    if (tid < NACT) s_ba[tid] = b_actor[tid];
    __syncthreads();

    const int warp = tid >> 5;
    const int lane = tid & 31;
    const int n = blockIdx.x * 8 + warp;

    const float* hrow = g_hidden + (size_t)n * HID;
    float h[16];
#pragma unroll
    for (int i = 0; i < 16; i++) h[i] = hrow[lane + 32 * i];

    float l[NACT];
#pragma unroll
    for (int a = 0; a < NACT; a++) {
        float p = 0.f;
        const float* wa = s_wa + a * HID;
#pragma unroll
        for (int i = 0; i < 16; i++) p += h[i] * wa[lane + 32 * i];
#pragma unroll
        for (int o = 16; o > 0; o >>= 1) p += __shfl_xor_sync(0xffffffffu, p, o);
        l[a] = p + s_ba[a];
    }

    float v = 0.f;
#pragma unroll
    for (int i = 0; i < 16; i++) v += h[i] * s_wc[lane + 32 * i];
#pragma unroll
    for (int o = 16; o > 0; o >>= 1) v += __shfl_xor_sync(0xffffffffu, v, o);
    v += b_critic[0];

    float mx = l[0];
#pragma unroll
    for (int a = 1; a < NACT; a++) mx = fmaxf(mx, l[a]);
    float s = 0.f;
#pragma unroll
    for (int a = 0; a < NACT; a++) s += expf(l[a] - mx);
    float lse = mx + logf(s);

    float ent = 0.f;
#pragma unroll
    for (int a = 0; a < NACT; a++) ent += expf(l[a] - lse) * (lse - l[a]);

    int act = action[n];
    float lp = 0.f;
#pragma unroll
    for (int a = 0; a < NACT; a++) lp += (a == act) ? (l[a] - lse) : 0.f;

    if (lane == 0) {
        out[n] = lp;
        out[NTOT + n] = ent;
        out[2 * NTOT + n] = v;
    }
}

// ---------------------------------------------------------------------------
extern "C" void kernel_launch(void* const* d_in, const int* in_sizes, int n_in,
                              void* d_out, int out_size)
{
    const float* x        = (const float*)d_in[0];
    const float* gru_st   = (const float*)d_in[1];
    const float* done     = (const float*)d_in[2];
    const int*   action   = (const int*)  d_in[3];
    const float* w1       = (const float*)d_in[4];
    const float* b1       = (const float*)d_in[5];
    const float* w2       = (const float*)d_in[6];
    const float* b2       = (const float*)d_in[7];
    const float* w_ih     = (const float*)d_in[8];
    const float* w_hh     = (const float*)d_in[9];
    const float* b_ih     = (const float*)d_in[10];
    const float* b_hh     = (const float*)d_in[11];
    const float* w_actor  = (const float*)d_in[12];
    const float* b_actor  = (const float*)d_in[13];
    const float* w_critic = (const float*)d_in[14];
    const float* b_critic = (const float*)d_in[15];
    float* out = (float*)d_out;

    float *h1, *h2, *gx, *bc;
    cudaGetSymbolAddress((void**)&h1, g_h1);
    cudaGetSymbolAddress((void**)&h2, g_h2);
    cudaGetSymbolAddress((void**)&gx, g_gx);
    cudaGetSymbolAddress((void**)&bc, g_bcomb);

    static int attrs_set = 0;
    if (!attrs_set) {
        cudaFuncSetAttribute(gru_scan_kernel,
                             cudaFuncAttributeMaxDynamicSharedMemorySize,
                             SCAN_SMEM_BYTES);
        attrs_set = 1;
    }

    // barriers + combined bias (b_ih + b_hh for r,z gates)
    init_kernel<<<(3 * HID + 255) / 256, 256>>>(b_ih, b_hh);

    // encoder layer 1: (N,512)@(512,256)^T -> h1
    gemm_f16_kernel<true><<<dim3(ENCD / 128, NTOT / 128), 256>>>(
        x, w1, b1, h1, NTOT, ENCD, OBSD);
    // encoder layer 2: (N,256)@(256,256)^T -> h2
    gemm_f16_kernel<true><<<dim3(ENCD / 128, NTOT / 128), 256>>>(
        h1, w2, b2, h2, NTOT, ENCD, ENCD);
    // input-side gates (bias = b_ih + b_hh[r,z]): (N,256)@(256,1536)^T -> gx
    gemm_f16_kernel<false><<<dim3(3 * HID / 128, NTOT / 128), 256>>>(
        h2, w_ih, bc, gx, NTOT, 3 * HID, ENCD);

    // persistent GRU scan
    gru_scan_kernel<<<N_GROUPS * BLKS_PER_GROUP, 256, SCAN_SMEM_BYTES>>>(
        gru_st, w_hh, b_hh, done, out + 3 * NTOT);

    heads_kernel<<<NTOT / 8, 256>>>(action, w_actor, b_actor, w_critic, b_critic, out);
}